// round 4
// baseline (speedup 1.0000x reference)
#include <cuda_runtime.h>
#include <math.h>
#include <stdint.h>

// Problem constants
#define BB 128            // batch
#define NN 1024           // nodes
#define UU 128            // rnn units
#define CIN 129           // OD + U
#define NM 3              // diffusion matrices
#define KTRUE 387         // CIN*NM
#define KPAD 400          // padded K (multiple of 16)
#define MROWS 131072      // B*N
#define MAX_NNZ 64
#define NTILES (KPAD / 16) // 25

// ---------------- scratch (static device globals; no allocation) -------------
__device__ float g_Xcat[(size_t)MROWS * KPAD];     // [row][k] k = s*129 + c, padded
__device__ float g_rh[(size_t)MROWS * UU];         // r * h
__device__ float g_u [(size_t)MROWS * UU];         // u gate
__device__ float g_Wg[KPAD * 256];                 // gate weights, k-major (s*129+c)
__device__ float g_Wc[KPAD * 128];                 // cand weights, k-major
__device__ int   g_csr_cnt[NN];
__device__ int   g_csr_col[NN * MAX_NNZ];
__device__ float g_csr_val[NN * MAX_NNZ];

// ---------------- cp.async helpers ------------------------------------------
__device__ __forceinline__ unsigned smem_u32(const void* p) {
    return (unsigned)__cvta_generic_to_shared(p);
}
__device__ __forceinline__ void cp16(unsigned dst, const void* src) {
    asm volatile("cp.async.cg.shared.global [%0], [%1], 16;" :: "r"(dst), "l"(src));
}
__device__ __forceinline__ void cp_commit() { asm volatile("cp.async.commit_group;"); }
__device__ __forceinline__ void cp_wait0()  { asm volatile("cp.async.wait_group 0;"); }

// ---------------- CSR build from dense support (per-launch, deterministic) ---
__global__ void csr_build(const float* __restrict__ S) {
    int w = (blockIdx.x * blockDim.x + threadIdx.x) >> 5;   // warp = row
    int lane = threadIdx.x & 31;
    if (w >= NN) return;
    const float* row = S + (size_t)w * NN;
    int cnt = 0;
    for (int base = 0; base < NN; base += 32) {
        float v = row[base + lane];
        unsigned m = __ballot_sync(0xffffffffu, v != 0.f);
        if (v != 0.f) {
            int pos = cnt + __popc(m & ((1u << lane) - 1u));
            if (pos < MAX_NNZ) {
                g_csr_col[w * MAX_NNZ + pos] = base + lane;
                g_csr_val[w * MAX_NNZ + pos] = v;
            }
        }
        cnt += __popc(m);
    }
    if (lane == 0) g_csr_cnt[w] = cnt < MAX_NNZ ? cnt : MAX_NNZ;
}

// ---------------- weight permutation: W[(c*3+s)*ld + j] -> Wt[(s*129+c)*ld+j]
template <int LD>
__global__ void wtrans(const float* __restrict__ W) {
    int k = blockIdx.x;
    int j = threadIdx.x;
    if (j >= LD) return;
    float v = 0.f;
    if (k < KTRUE) {
        int c = k % CIN, s = k / CIN;
        v = W[(size_t)(c * NM + s) * LD + j];
    }
    float* Wt = (LD == 256) ? g_Wg : g_Wc;
    Wt[(size_t)k * LD + j] = v;
}

// ---------------- diffusion pass 1: writes x0 (cols 0..128), x1 (129..257), pad
// USE_RH=0: hidden source is hvec param (h input); USE_RH=1: source is g_rh.
template <int USE_RH>
__global__ void spmm_pass1(const float* __restrict__ inp, const float* __restrict__ hparam) {
    const float* __restrict__ hvec = USE_RH ? (const float*)g_rh : hparam;
    int m = blockIdx.x, b = blockIdx.y, tid = threadIdx.x;
    __shared__ int scol[MAX_NNZ];
    __shared__ float sval[MAX_NNZ];
    int cnt = g_csr_cnt[m];
    if (tid < MAX_NNZ) {
        scol[tid] = g_csr_col[m * MAX_NNZ + tid];
        sval[tid] = g_csr_val[m * MAX_NNZ + tid];
    }
    __syncthreads();
    size_t rowm = (size_t)b * NN + m;
    float a0 = 0.f, a1 = 0.f;
    for (int i = 0; i < cnt; i++) {
        int n = scol[i];
        float s = sval[i];
        size_t rn = (size_t)b * NN + n;
        float x = (tid == 0) ? inp[rn] : hvec[rn * UU + tid - 1];
        a0 += s * x;
        if (tid == 0) a1 += s * hvec[rn * UU + 127];
    }
    float* X = g_Xcat + rowm * KPAD;
    X[129 + tid] = a0;
    float xo = (tid == 0) ? inp[rowm] : hvec[rowm * UU + tid - 1];
    X[tid] = xo;
    if (tid == 0) {
        X[129 + 128] = a1;
        X[128] = hvec[rowm * UU + 127];
    }
    if (tid < KPAD - KTRUE) X[KTRUE + tid] = 0.f;   // zero pad cols 387..399
}

// ---------------- diffusion pass 2: x2 = 2*S@x1 - x0 (cols 258..386) --------
__global__ void spmm_pass2() {
    int m = blockIdx.x, b = blockIdx.y, tid = threadIdx.x;
    __shared__ int scol[MAX_NNZ];
    __shared__ float sval[MAX_NNZ];
    int cnt = g_csr_cnt[m];
    if (tid < MAX_NNZ) {
        scol[tid] = g_csr_col[m * MAX_NNZ + tid];
        sval[tid] = g_csr_val[m * MAX_NNZ + tid];
    }
    __syncthreads();
    size_t rowm = (size_t)b * NN + m;
    float a0 = 0.f, a1 = 0.f;
    for (int i = 0; i < cnt; i++) {
        int n = scol[i];
        float s = sval[i];
        const float* Xn = g_Xcat + ((size_t)b * NN + n) * KPAD + 129;
        a0 += s * Xn[tid];
        if (tid == 0) a1 += s * Xn[128];
    }
    const float* X0 = g_Xcat + rowm * KPAD;
    float* X2 = g_Xcat + rowm * KPAD + 258;
    X2[tid] = 2.f * a0 - X0[tid];
    if (tid == 0) X2[128] = 2.f * a1 - X0[128];
}

// ---------------- fp32 SGEMM, BM=128 BN=128 BK=16, 256 thr, 8x8/thread ------
// Double-buffered smem. B via cp.async (no staging regs); A ldg issued before
// compute (latency hidden), scatter-stored to the other buffer after compute.
// One __syncthreads per k-tile. No forced occupancy -> no spill possible.
// MODE 0: gate (B=g_Wg, LDB=256, grid.y=2).
//         by==0 -> g_rh = sigmoid(acc+b) * h ;  by==1 -> g_u = sigmoid(acc+b)
// MODE 1: cand (B=g_Wc, LDB=128, grid.y=1).  newh = u*h + (1-u)*tanh(acc+b)
template <int MODE>
__global__ void __launch_bounds__(256) gemm_kernel(
    const float* __restrict__ bias, const float* __restrict__ hvec,
    float* __restrict__ newh)
{
    constexpr int LDB = (MODE == 0) ? 256 : 128;
    const float* __restrict__ Bw = (MODE == 0) ? g_Wg : g_Wc;
    __shared__ float As[2][16][132];
    __shared__ float Bs[2][16][128];
    int tid = threadIdx.x;
    int tx = tid & 15, ty = tid >> 4;
    const size_t mbase = (size_t)blockIdx.x * 128;
    const int jbase = blockIdx.y * 128;
    const float* Ab = g_Xcat + mbase * KPAD;
    const float* Bb = Bw + jbase;

    // per-thread load coordinates (2 chunks each for A and B)
    const int ar0 = (tid * 2) >> 3,     ak0 = ((tid * 2) & 7) * 2;      // A: f=2*tid
    const int ar1 = (tid * 2 + 1) >> 3, ak1 = ((tid * 2 + 1) & 7) * 2;  // (r, k/2)
    // A chunk i covers As rows r = f>>3 ... wait: use same mapping as before:
    // f in [0,512): r = f>>2, kk=(f&3)*4  -> thread handles f=tid and f=tid+256
    const int r0 = tid >> 2,        kk0 = (tid & 3) * 4;
    const int r1 = (tid + 256) >> 2, kk1 = ((tid + 256) & 3) * 4;
    const int kb0 = tid >> 5,        jb0 = (tid & 31) * 4;
    const int kb1 = (tid + 256) >> 5, jb1 = ((tid + 256) & 31) * 4;
    (void)ar0; (void)ak0; (void)ar1; (void)ak1;

    float acc[8][8];
#pragma unroll
    for (int i = 0; i < 8; i++)
#pragma unroll
        for (int j = 0; j < 8; j++) acc[i][j] = 0.f;

    // ---- preamble: tile 0 into buffer 0
    {
        float4 va0 = *(const float4*)(Ab + (size_t)r0 * KPAD + kk0);
        float4 va1 = *(const float4*)(Ab + (size_t)r1 * KPAD + kk1);
        As[0][kk0 + 0][r0] = va0.x; As[0][kk0 + 1][r0] = va0.y;
        As[0][kk0 + 2][r0] = va0.z; As[0][kk0 + 3][r0] = va0.w;
        As[0][kk1 + 0][r1] = va1.x; As[0][kk1 + 1][r1] = va1.y;
        As[0][kk1 + 2][r1] = va1.z; As[0][kk1 + 3][r1] = va1.w;
        cp16(smem_u32(&Bs[0][kb0][jb0]), Bb + (size_t)kb0 * LDB + jb0);
        cp16(smem_u32(&Bs[0][kb1][jb1]), Bb + (size_t)kb1 * LDB + jb1);
        cp_commit();
    }

    for (int t = 0; t < NTILES; t++) {
        int cur = t & 1, nxt = cur ^ 1;
        cp_wait0();
        __syncthreads();

        float4 va0, va1;
        bool more = (t + 1) < NTILES;
        if (more) {
            int k0 = (t + 1) * 16;
            va0 = *(const float4*)(Ab + (size_t)r0 * KPAD + k0 + kk0);
            va1 = *(const float4*)(Ab + (size_t)r1 * KPAD + k0 + kk1);
            cp16(smem_u32(&Bs[nxt][kb0][jb0]), Bb + (size_t)(k0 + kb0) * LDB + jb0);
            cp16(smem_u32(&Bs[nxt][kb1][jb1]), Bb + (size_t)(k0 + kb1) * LDB + jb1);
            cp_commit();
        }

#pragma unroll
        for (int k = 0; k < 16; k++) {
            float a[8], b[8];
            *(float4*)&a[0] = *(const float4*)&As[cur][k][ty * 8];
            *(float4*)&a[4] = *(const float4*)&As[cur][k][ty * 8 + 4];
            *(float4*)&b[0] = *(const float4*)&Bs[cur][k][tx * 8];
            *(float4*)&b[4] = *(const float4*)&Bs[cur][k][tx * 8 + 4];
#pragma unroll
            for (int ii = 0; ii < 8; ii++)
#pragma unroll
                for (int jj = 0; jj < 8; jj++)
                    acc[ii][jj] = fmaf(a[ii], b[jj], acc[ii][jj]);
        }

        if (more) {   // A global loads long arrived; store into next buffer
            As[nxt][kk0 + 0][r0] = va0.x; As[nxt][kk0 + 1][r0] = va0.y;
            As[nxt][kk0 + 2][r0] = va0.z; As[nxt][kk0 + 3][r0] = va0.w;
            As[nxt][kk1 + 0][r1] = va1.x; As[nxt][kk1 + 1][r1] = va1.y;
            As[nxt][kk1 + 2][r1] = va1.z; As[nxt][kk1 + 3][r1] = va1.w;
        }
    }

    // epilogue (write directly, no staging array)
#pragma unroll
    for (int ii = 0; ii < 8; ii++) {
        size_t row = mbase + ty * 8 + ii;
#pragma unroll
        for (int jj = 0; jj < 8; jj++) {
            int jg = jbase + tx * 8 + jj;
            float v = acc[ii][jj] + bias[jg];
            if (MODE == 0) {
                float sg = 1.f / (1.f + expf(-v));
                if (jbase == 0) {
                    g_rh[row * UU + jg] = sg * hvec[row * UU + jg];      // r*h
                } else {
                    g_u[row * UU + (jg - 128)] = sg;                      // u
                }
            } else {
                float c = tanhf(v);
                size_t idx = row * UU + jg;
                float u = g_u[idx];
                newh[idx] = u * hvec[idx] + (1.f - u) * c;                // new_h
            }
        }
    }
}

// ---------------- projection: out[row] = dot(new_h[row,:], proj_w) + pb -----
__global__ void proj_kernel(const float* __restrict__ newh,
                            const float* __restrict__ pw,
                            const float* __restrict__ pb,
                            float* __restrict__ out) {
    int gw = (blockIdx.x * blockDim.x + threadIdx.x) >> 5;
    int lane = threadIdx.x & 31;
    if (gw >= MROWS) return;
    float4 v = *(const float4*)(newh + (size_t)gw * UU + lane * 4);
    float4 w = *(const float4*)(pw + lane * 4);
    float d = v.x * w.x + v.y * w.y + v.z * w.z + v.w * w.w;
#pragma unroll
    for (int off = 16; off > 0; off >>= 1)
        d += __shfl_xor_sync(0xffffffffu, d, off);
    if (lane == 0) out[gw] = d + pb[0];
}

// ---------------- launch: kernel launches ONLY; no device symbols touched ---
extern "C" void kernel_launch(void* const* d_in, const int* in_sizes, int n_in,
                              void* d_out, int out_size) {
    const float* inp = (const float*)d_in[0];   // (B, N)
    const float* h   = (const float*)d_in[1];   // (1, B, N*U)
    const float* S   = (const float*)d_in[2];   // (N, N)
    const float* gw  = (const float*)d_in[3];   // (387, 256)
    const float* gb  = (const float*)d_in[4];   // (256,)
    const float* cw  = (const float*)d_in[5];   // (387, 128)
    const float* cb  = (const float*)d_in[6];   // (128,)
    const float* pw  = (const float*)d_in[7];   // (128, 1)
    const float* pb  = (const float*)d_in[8];   // (1,)
    float* out  = (float*)d_out;                // output: 131072 floats
    float* newh = out + MROWS;                  // new_h:  16777216 floats

    // 1. sparsify support + permute weights (cheap, per launch, deterministic)
    csr_build<<<128, 256>>>(S);
    wtrans<256><<<KPAD, 256>>>(gw);
    wtrans<128><<<KPAD, 128>>>(cw);

    // 2. gate path: diffusion of [inputs | h], then gate GEMM (sigmoid fused)
    spmm_pass1<0><<<dim3(NN, BB), 128>>>(inp, h);
    spmm_pass2<<<dim3(NN, BB), 128>>>();
    gemm_kernel<0><<<dim3(MROWS / 128, 2), 256>>>(gb, h, nullptr);

    // 3. cand path: diffusion of [inputs | r*h], cand GEMM (tanh + GRU fused)
    spmm_pass1<1><<<dim3(NN, BB), 128>>>(inp, nullptr);
    spmm_pass2<<<dim3(NN, BB), 128>>>();
    gemm_kernel<1><<<dim3(MROWS / 128, 1), 256>>>(cb, h, newh);

    // 4. projection
    proj_kernel<<<MROWS / 8, 256>>>(newh, pw, pb, out);
}

// round 5
// speedup vs baseline: 1.4424x; 1.4424x over previous
#include <cuda_runtime.h>
#include <math.h>
#include <stdint.h>

// Problem constants
#define BB 128            // batch
#define NN 1024           // nodes
#define UU 128            // rnn units
#define NM 3              // diffusion matrices
#define SBLK 132          // per-step channel block: 128 hvec + 1 inp + 3 pad
#define KPAD 400          // padded K (3*132=396 -> 400, multiple of 16)
#define MROWS 131072      // B*N
#define MAX_NNZ 64
#define NTILES (KPAD / 16) // 25

// Xcat row layout (stride KPAD):
//   [0..127]   x0 hvec     [128] x0 inp     [129..131] pad
//   [132..259] x1 hvec     [260] x1 inp     [261..263] pad
//   [264..391] x2 hvec     [392] x2 inp     [393..399] pad

// ---------------- scratch (static device globals; no allocation) -------------
__device__ float g_Xcat[(size_t)MROWS * KPAD];
__device__ float g_rh[(size_t)MROWS * UU];         // r * h
__device__ float g_u [(size_t)MROWS * UU];         // u gate
__device__ float g_Wg[KPAD * 256];                 // gate weights, new k-major
__device__ float g_Wc[KPAD * 128];                 // cand weights, new k-major
__device__ int   g_csr_cnt[NN];
__device__ int   g_csr_col[NN * MAX_NNZ];
__device__ float g_csr_val[NN * MAX_NNZ];

// ---------------- cp.async helpers ------------------------------------------
__device__ __forceinline__ unsigned smem_u32(const void* p) {
    return (unsigned)__cvta_generic_to_shared(p);
}
__device__ __forceinline__ void cp16(unsigned dst, const void* src) {
    asm volatile("cp.async.cg.shared.global [%0], [%1], 16;" :: "r"(dst), "l"(src));
}
__device__ __forceinline__ void cp_commit() { asm volatile("cp.async.commit_group;"); }
__device__ __forceinline__ void cp_wait0()  { asm volatile("cp.async.wait_group 0;"); }

// ---------------- CSR build from dense support (per-launch, deterministic) ---
__global__ void csr_build(const float* __restrict__ S) {
    int w = (blockIdx.x * blockDim.x + threadIdx.x) >> 5;   // warp = row
    int lane = threadIdx.x & 31;
    if (w >= NN) return;
    const float* row = S + (size_t)w * NN;
    int cnt = 0;
    for (int base = 0; base < NN; base += 32) {
        float v = row[base + lane];
        unsigned m = __ballot_sync(0xffffffffu, v != 0.f);
        if (v != 0.f) {
            int pos = cnt + __popc(m & ((1u << lane) - 1u));
            if (pos < MAX_NNZ) {
                g_csr_col[w * MAX_NNZ + pos] = base + lane;
                g_csr_val[w * MAX_NNZ + pos] = v;
            }
        }
        cnt += __popc(m);
    }
    if (lane == 0) g_csr_cnt[w] = cnt < MAX_NNZ ? cnt : MAX_NNZ;
}

// ---------------- weight permutation ----------------------------------------
// Reference k index = c_orig*NM + s  (c_orig: 0=inp, 1..128=hvec 0..127).
// New k index = s*SBLK + c_new (c_new: 0..127=hvec, 128=inp, 129..131 pad).
template <int LD>
__global__ void wtrans(const float* __restrict__ W) {
    int k = blockIdx.x;
    int j = threadIdx.x;
    int s = k / SBLK, c = k % SBLK;
    float v = 0.f;
    if (s < NM && c < 129) {
        int corig = (c == 128) ? 0 : (c + 1);
        v = W[(size_t)(corig * NM + s) * LD + j];
    }
    float* Wt = (LD == 256) ? g_Wg : g_Wc;
    Wt[(size_t)k * LD + j] = v;
}

// ---------------- diffusion pass 1 (vectorized) ------------------------------
// Block = 128 thr = 4 batch-groups x 32 lanes; grid = (NN, BB/4).
// Writes x0 copy + x1 = S@x0 + zeroes all pad columns.
// USE_RH=0: hidden source = hparam; USE_RH=1: source = g_rh.
template <int USE_RH>
__global__ void __launch_bounds__(128) spmm_pass1(
    const float* __restrict__ inp, const float* __restrict__ hparam)
{
    const float* __restrict__ hvec = USE_RH ? (const float*)g_rh : hparam;
    int m = blockIdx.x;
    int g = threadIdx.x >> 5, lane = threadIdx.x & 31;
    int b = blockIdx.y * 4 + g;
    __shared__ int   scol[MAX_NNZ];
    __shared__ float sval[MAX_NNZ];
    __shared__ float sinp[4][MAX_NNZ];
    int cnt = g_csr_cnt[m];
    if (threadIdx.x < MAX_NNZ) {
        scol[threadIdx.x] = g_csr_col[m * MAX_NNZ + threadIdx.x];
        sval[threadIdx.x] = g_csr_val[m * MAX_NNZ + threadIdx.x];
    }
    __syncthreads();
    if (lane < cnt) sinp[g][lane] = inp[(size_t)b * NN + scol[lane]];
    if (cnt > 32 && lane + 32 < cnt) sinp[g][lane + 32] = inp[(size_t)b * NN + scol[lane + 32]];
    __syncwarp();

    size_t rowm = (size_t)b * NN + m;
    float4 a = make_float4(0.f, 0.f, 0.f, 0.f);
    float a1 = 0.f;
    for (int i = 0; i < cnt; i++) {
        float s = sval[i];
        const float4* hp = (const float4*)(hvec + ((size_t)b * NN + scol[i]) * UU);
        float4 hv = hp[lane];
        a.x = fmaf(s, hv.x, a.x);
        a.y = fmaf(s, hv.y, a.y);
        a.z = fmaf(s, hv.z, a.z);
        a.w = fmaf(s, hv.w, a.w);
        if (lane == 0) a1 = fmaf(s, sinp[g][i], a1);
    }

    float* X = g_Xcat + rowm * KPAD;
    // x0 copy
    ((float4*)X)[lane] = ((const float4*)(hvec + rowm * UU))[lane];
    // x1
    *(float4*)(X + 132 + lane * 4) = a;
    if (lane == 0) {
        X[128] = inp[rowm];
        X[260] = a1;
    }
    // zero all pad columns (x2 pads too; pass2 won't touch them)
    if (lane < 3) {
        X[129 + lane] = 0.f;
        X[261 + lane] = 0.f;
        X[393 + lane] = 0.f;
    }
    if (lane < 4) X[396 + lane] = 0.f;
}

// ---------------- diffusion pass 2 (vectorized): x2 = 2*S@x1 - x0 -----------
__global__ void __launch_bounds__(128) spmm_pass2() {
    int m = blockIdx.x;
    int g = threadIdx.x >> 5, lane = threadIdx.x & 31;
    int b = blockIdx.y * 4 + g;
    __shared__ int   scol[MAX_NNZ];
    __shared__ float sval[MAX_NNZ];
    __shared__ float sx1i[4][MAX_NNZ];
    int cnt = g_csr_cnt[m];
    if (threadIdx.x < MAX_NNZ) {
        scol[threadIdx.x] = g_csr_col[m * MAX_NNZ + threadIdx.x];
        sval[threadIdx.x] = g_csr_val[m * MAX_NNZ + threadIdx.x];
    }
    __syncthreads();
    if (lane < cnt) sx1i[g][lane] = g_Xcat[((size_t)b * NN + scol[lane]) * KPAD + 260];
    if (cnt > 32 && lane + 32 < cnt) sx1i[g][lane + 32] = g_Xcat[((size_t)b * NN + scol[lane + 32]) * KPAD + 260];
    __syncwarp();

    size_t rowm = (size_t)b * NN + m;
    float4 a = make_float4(0.f, 0.f, 0.f, 0.f);
    float a1 = 0.f;
    for (int i = 0; i < cnt; i++) {
        float s = sval[i];
        const float4* xp = (const float4*)(g_Xcat + ((size_t)b * NN + scol[i]) * KPAD + 132);
        float4 hv = xp[lane];
        a.x = fmaf(s, hv.x, a.x);
        a.y = fmaf(s, hv.y, a.y);
        a.z = fmaf(s, hv.z, a.z);
        a.w = fmaf(s, hv.w, a.w);
        if (lane == 0) a1 = fmaf(s, sx1i[g][i], a1);
    }

    float* X = g_Xcat + rowm * KPAD;
    float4 x0 = ((const float4*)X)[lane];
    float4 r;
    r.x = 2.f * a.x - x0.x;
    r.y = 2.f * a.y - x0.y;
    r.z = 2.f * a.z - x0.z;
    r.w = 2.f * a.w - x0.w;
    *(float4*)(X + 264 + lane * 4) = r;
    if (lane == 0) X[392] = 2.f * a1 - X[128];
}

// ---------------- fp32 SGEMM, BM=128 BN=128 BK=16, 256 thr, 8x8/thread ------
// Double-buffered smem. B via cp.async; A ldg issued before compute.
// MODE 0: gate (B=g_Wg, LDB=256, grid.y=2).
//         by==0 -> g_rh = sigmoid(acc+b) * h ;  by==1 -> g_u = sigmoid(acc+b)
// MODE 1: cand (B=g_Wc, LDB=128, grid.y=1).  newh = u*h + (1-u)*tanh(acc+b)
template <int MODE>
__global__ void __launch_bounds__(256) gemm_kernel(
    const float* __restrict__ bias, const float* __restrict__ hvec,
    float* __restrict__ newh)
{
    constexpr int LDB = (MODE == 0) ? 256 : 128;
    const float* __restrict__ Bw = (MODE == 0) ? g_Wg : g_Wc;
    __shared__ float As[2][16][132];
    __shared__ float Bs[2][16][128];
    int tid = threadIdx.x;
    int tx = tid & 15, ty = tid >> 4;
    const size_t mbase = (size_t)blockIdx.x * 128;
    const int jbase = blockIdx.y * 128;
    const float* Ab = g_Xcat + mbase * KPAD;
    const float* Bb = Bw + jbase;

    const int r0 = tid >> 2,         kk0 = (tid & 3) * 4;
    const int r1 = (tid + 256) >> 2, kk1 = ((tid + 256) & 3) * 4;
    const int kb0 = tid >> 5,        jb0 = (tid & 31) * 4;
    const int kb1 = (tid + 256) >> 5, jb1 = ((tid + 256) & 31) * 4;

    float acc[8][8];
#pragma unroll
    for (int i = 0; i < 8; i++)
#pragma unroll
        for (int j = 0; j < 8; j++) acc[i][j] = 0.f;

    // preamble: tile 0 into buffer 0
    {
        float4 va0 = *(const float4*)(Ab + (size_t)r0 * KPAD + kk0);
        float4 va1 = *(const float4*)(Ab + (size_t)r1 * KPAD + kk1);
        As[0][kk0 + 0][r0] = va0.x; As[0][kk0 + 1][r0] = va0.y;
        As[0][kk0 + 2][r0] = va0.z; As[0][kk0 + 3][r0] = va0.w;
        As[0][kk1 + 0][r1] = va1.x; As[0][kk1 + 1][r1] = va1.y;
        As[0][kk1 + 2][r1] = va1.z; As[0][kk1 + 3][r1] = va1.w;
        cp16(smem_u32(&Bs[0][kb0][jb0]), Bb + (size_t)kb0 * LDB + jb0);
        cp16(smem_u32(&Bs[0][kb1][jb1]), Bb + (size_t)kb1 * LDB + jb1);
        cp_commit();
    }

    for (int t = 0; t < NTILES; t++) {
        int cur = t & 1, nxt = cur ^ 1;
        cp_wait0();
        __syncthreads();

        float4 va0, va1;
        bool more = (t + 1) < NTILES;
        if (more) {
            int k0 = (t + 1) * 16;
            va0 = *(const float4*)(Ab + (size_t)r0 * KPAD + k0 + kk0);
            va1 = *(const float4*)(Ab + (size_t)r1 * KPAD + k0 + kk1);
            cp16(smem_u32(&Bs[nxt][kb0][jb0]), Bb + (size_t)(k0 + kb0) * LDB + jb0);
            cp16(smem_u32(&Bs[nxt][kb1][jb1]), Bb + (size_t)(k0 + kb1) * LDB + jb1);
            cp_commit();
        }

#pragma unroll
        for (int k = 0; k < 16; k++) {
            float a[8], b[8];
            *(float4*)&a[0] = *(const float4*)&As[cur][k][ty * 8];
            *(float4*)&a[4] = *(const float4*)&As[cur][k][ty * 8 + 4];
            *(float4*)&b[0] = *(const float4*)&Bs[cur][k][tx * 8];
            *(float4*)&b[4] = *(const float4*)&Bs[cur][k][tx * 8 + 4];
#pragma unroll
            for (int ii = 0; ii < 8; ii++)
#pragma unroll
                for (int jj = 0; jj < 8; jj++)
                    acc[ii][jj] = fmaf(a[ii], b[jj], acc[ii][jj]);
        }

        if (more) {
            As[nxt][kk0 + 0][r0] = va0.x; As[nxt][kk0 + 1][r0] = va0.y;
            As[nxt][kk0 + 2][r0] = va0.z; As[nxt][kk0 + 3][r0] = va0.w;
            As[nxt][kk1 + 0][r1] = va1.x; As[nxt][kk1 + 1][r1] = va1.y;
            As[nxt][kk1 + 2][r1] = va1.z; As[nxt][kk1 + 3][r1] = va1.w;
        }
    }

    // epilogue
#pragma unroll
    for (int ii = 0; ii < 8; ii++) {
        size_t row = mbase + ty * 8 + ii;
#pragma unroll
        for (int jj = 0; jj < 8; jj++) {
            int jg = jbase + tx * 8 + jj;
            float v = acc[ii][jj] + bias[jg];
            if (MODE == 0) {
                float sg = 1.f / (1.f + expf(-v));
                if (jbase == 0) {
                    g_rh[row * UU + jg] = sg * hvec[row * UU + jg];      // r*h
                } else {
                    g_u[row * UU + (jg - 128)] = sg;                      // u
                }
            } else {
                float c = tanhf(v);
                size_t idx = row * UU + jg;
                float u = g_u[idx];
                newh[idx] = u * hvec[idx] + (1.f - u) * c;                // new_h
            }
        }
    }
}

// ---------------- projection: out[row] = dot(new_h[row,:], proj_w) + pb -----
__global__ void proj_kernel(const float* __restrict__ newh,
                            const float* __restrict__ pw,
                            const float* __restrict__ pb,
                            float* __restrict__ out) {
    int gw = (blockIdx.x * blockDim.x + threadIdx.x) >> 5;
    int lane = threadIdx.x & 31;
    if (gw >= MROWS) return;
    float4 v = *(const float4*)(newh + (size_t)gw * UU + lane * 4);
    float4 w = *(const float4*)(pw + lane * 4);
    float d = v.x * w.x + v.y * w.y + v.z * w.z + v.w * w.w;
#pragma unroll
    for (int off = 16; off > 0; off >>= 1)
        d += __shfl_xor_sync(0xffffffffu, d, off);
    if (lane == 0) out[gw] = d + pb[0];
}

// ---------------- launch: kernel launches ONLY; no device symbols touched ---
extern "C" void kernel_launch(void* const* d_in, const int* in_sizes, int n_in,
                              void* d_out, int out_size) {
    const float* inp = (const float*)d_in[0];   // (B, N)
    const float* h   = (const float*)d_in[1];   // (1, B, N*U)
    const float* S   = (const float*)d_in[2];   // (N, N)
    const float* gw  = (const float*)d_in[3];   // (387, 256)
    const float* gb  = (const float*)d_in[4];   // (256,)
    const float* cw  = (const float*)d_in[5];   // (387, 128)
    const float* cb  = (const float*)d_in[6];   // (128,)
    const float* pw  = (const float*)d_in[7];   // (128, 1)
    const float* pb  = (const float*)d_in[8];   // (1,)
    float* out  = (float*)d_out;                // output: 131072 floats
    float* newh = out + MROWS;                  // new_h:  16777216 floats

    // 1. sparsify support + permute weights
    csr_build<<<128, 256>>>(S);
    wtrans<256><<<KPAD, 256>>>(gw);
    wtrans<128><<<KPAD, 128>>>(cw);

    // 2. gate path
    spmm_pass1<0><<<dim3(NN, BB / 4), 128>>>(inp, h);
    spmm_pass2<<<dim3(NN, BB / 4), 128>>>();
    gemm_kernel<0><<<dim3(MROWS / 128, 2), 256>>>(gb, h, nullptr);

    // 3. cand path
    spmm_pass1<1><<<dim3(NN, BB / 4), 128>>>(inp, nullptr);
    spmm_pass2<<<dim3(NN, BB / 4), 128>>>();
    gemm_kernel<1><<<dim3(MROWS / 128, 1), 256>>>(cb, h, newh);

    // 4. projection
    proj_kernel<<<MROWS / 8, 256>>>(newh, pw, pb, out);
}

// round 6
// speedup vs baseline: 2.1845x; 1.5146x over previous
#include <cuda_runtime.h>
#include <cuda_bf16.h>
#include <math.h>
#include <stdint.h>

// Problem constants
#define BB 128
#define NN 1024
#define UU 128
#define NM 3
#define SBLK 132           // per-step block: 128 hvec + 1 inp + 3 pad
#define KPAD 416           // 3*132 = 396 -> 416 (26 x 16)
#define NCH (KPAD / 16)    // 26 k-chunks
#define MROWS 131072
#define MAX_NNZ 64

// Xhi/Xlo row layout (stride KPAD, bf16):
//   [0..127] x0 hvec  [128] x0 inp [129..131] pad
//   [132..259] x1     [260] x1 inp [261..263] pad
//   [264..391] x2     [392] x2 inp [393..415] pad

// ---------------- scratch -----------------------------------------------------
__device__ float         g_X1f[(size_t)MROWS * 132];   // fp32 x1 for pass2 gather
__device__ __nv_bfloat16 g_Xhi[(size_t)MROWS * KPAD];
__device__ __nv_bfloat16 g_Xlo[(size_t)MROWS * KPAD];
__device__ float g_rh[(size_t)MROWS * UU];
__device__ float g_u [(size_t)MROWS * UU];
__device__ __nv_bfloat16 g_Wgt_hi[256 * KPAD];         // gate W^T [N][K]
__device__ __nv_bfloat16 g_Wgt_lo[256 * KPAD];
__device__ __nv_bfloat16 g_Wct_hi[128 * KPAD];         // cand W^T [N][K]
__device__ __nv_bfloat16 g_Wct_lo[128 * KPAD];
__device__ int   g_csr_cnt[NN];
__device__ int   g_csr_col[NN * MAX_NNZ];
__device__ float g_csr_val[NN * MAX_NNZ];

// ---------------- helpers -----------------------------------------------------
__device__ __forceinline__ unsigned smem_u32(const void* p) {
    return (unsigned)__cvta_generic_to_shared(p);
}
__device__ __forceinline__ void cp16(unsigned dst, const void* src) {
    asm volatile("cp.async.cg.shared.global [%0], [%1], 16;" :: "r"(dst), "l"(src));
}
__device__ __forceinline__ void cp_commit() { asm volatile("cp.async.commit_group;"); }
__device__ __forceinline__ void cp_wait0()  { asm volatile("cp.async.wait_group 0;"); }

__device__ __forceinline__ void ldsm_x4(uint32_t* r, uint32_t a) {
    asm volatile("ldmatrix.sync.aligned.m8n8.x4.shared.b16 {%0,%1,%2,%3}, [%4];"
                 : "=r"(r[0]), "=r"(r[1]), "=r"(r[2]), "=r"(r[3]) : "r"(a));
}
__device__ __forceinline__ void ldsm_x2(uint32_t* r, uint32_t a) {
    asm volatile("ldmatrix.sync.aligned.m8n8.x2.shared.b16 {%0,%1}, [%2];"
                 : "=r"(r[0]), "=r"(r[1]) : "r"(a));
}
__device__ __forceinline__ void mma_bf16(float* c, const uint32_t* a, const uint32_t* b) {
    asm volatile("mma.sync.aligned.m16n8k16.row.col.f32.bf16.bf16.f32 "
                 "{%0,%1,%2,%3}, {%4,%5,%6,%7}, {%8,%9}, {%0,%1,%2,%3};"
                 : "+f"(c[0]), "+f"(c[1]), "+f"(c[2]), "+f"(c[3])
                 : "r"(a[0]), "r"(a[1]), "r"(a[2]), "r"(a[3]), "r"(b[0]), "r"(b[1]));
}

__device__ __forceinline__ uint32_t pk2(__nv_bfloat16 a, __nv_bfloat16 b) {
    return (uint32_t)__bfloat16_as_ushort(a) | ((uint32_t)__bfloat16_as_ushort(b) << 16);
}
__device__ __forceinline__ void split_store4(__nv_bfloat16* ph, __nv_bfloat16* pl, float4 v) {
    __nv_bfloat16 h0 = __float2bfloat16(v.x), h1 = __float2bfloat16(v.y),
                  h2 = __float2bfloat16(v.z), h3 = __float2bfloat16(v.w);
    __nv_bfloat16 l0 = __float2bfloat16(v.x - __bfloat162float(h0)),
                  l1 = __float2bfloat16(v.y - __bfloat162float(h1)),
                  l2 = __float2bfloat16(v.z - __bfloat162float(h2)),
                  l3 = __float2bfloat16(v.w - __bfloat162float(h3));
    uint2 uh; uh.x = pk2(h0, h1); uh.y = pk2(h2, h3);
    uint2 ul; ul.x = pk2(l0, l1); ul.y = pk2(l2, l3);
    *(uint2*)ph = uh; *(uint2*)pl = ul;
}
__device__ __forceinline__ void split_store1pad(__nv_bfloat16* ph, __nv_bfloat16* pl, float v) {
    __nv_bfloat16 h = __float2bfloat16(v);
    __nv_bfloat16 l = __float2bfloat16(v - __bfloat162float(h));
    uint2 uh; uh.x = pk2(h, __float2bfloat16(0.f)); uh.y = 0u;
    uint2 ul; ul.x = pk2(l, __float2bfloat16(0.f)); ul.y = 0u;
    *(uint2*)ph = uh; *(uint2*)pl = ul;
}

// ---------------- CSR build ---------------------------------------------------
__global__ void csr_build(const float* __restrict__ S) {
    int w = (blockIdx.x * blockDim.x + threadIdx.x) >> 5;
    int lane = threadIdx.x & 31;
    if (w >= NN) return;
    const float* row = S + (size_t)w * NN;
    int cnt = 0;
    for (int base = 0; base < NN; base += 32) {
        float v = row[base + lane];
        unsigned m = __ballot_sync(0xffffffffu, v != 0.f);
        if (v != 0.f) {
            int pos = cnt + __popc(m & ((1u << lane) - 1u));
            if (pos < MAX_NNZ) {
                g_csr_col[w * MAX_NNZ + pos] = base + lane;
                g_csr_val[w * MAX_NNZ + pos] = v;
            }
        }
        cnt += __popc(m);
    }
    if (lane == 0) g_csr_cnt[w] = cnt < MAX_NNZ ? cnt : MAX_NNZ;
}

// ---------------- weight transpose + bf16 split: -> Wt[n][k] ------------------
// ref k = c_orig*NM + s (c_orig 0 = inp, 1..128 = hvec); new k = s*SBLK + c_new.
template <int LD>
__global__ void wtrans(const float* __restrict__ W) {
    int k = blockIdx.x, j = threadIdx.x;
    int s = k / SBLK, c = k - s * SBLK;
    float v = 0.f;
    if (s < NM && c < 129) {
        int corig = (c == 128) ? 0 : (c + 1);
        v = W[(size_t)(corig * NM + s) * LD + j];
    }
    __nv_bfloat16 hi = __float2bfloat16(v);
    __nv_bfloat16 lo = __float2bfloat16(v - __bfloat162float(hi));
    if (LD == 256) {
        g_Wgt_hi[(size_t)j * KPAD + k] = hi;
        g_Wgt_lo[(size_t)j * KPAD + k] = lo;
    } else {
        g_Wct_hi[(size_t)j * KPAD + k] = hi;
        g_Wct_lo[(size_t)j * KPAD + k] = lo;
    }
}

// ---------------- diffusion pass 1: x0 split + x1 (=S@x0) --------------------
template <int USE_RH>
__global__ void __launch_bounds__(128) spmm_pass1(
    const float* __restrict__ inp, const float* __restrict__ hparam)
{
    const float* __restrict__ hvec = USE_RH ? (const float*)g_rh : hparam;
    int m = blockIdx.x;
    int g = threadIdx.x >> 5, lane = threadIdx.x & 31;
    int b = blockIdx.y * 4 + g;
    __shared__ int   scol[MAX_NNZ];
    __shared__ float sval[MAX_NNZ];
    __shared__ float sinp[4][MAX_NNZ];
    int cnt = g_csr_cnt[m];
    if (threadIdx.x < MAX_NNZ) {
        scol[threadIdx.x] = g_csr_col[m * MAX_NNZ + threadIdx.x];
        sval[threadIdx.x] = g_csr_val[m * MAX_NNZ + threadIdx.x];
    }
    __syncthreads();
    if (lane < cnt) sinp[g][lane] = inp[(size_t)b * NN + scol[lane]];
    if (cnt > 32 && lane + 32 < cnt) sinp[g][lane + 32] = inp[(size_t)b * NN + scol[lane + 32]];
    __syncwarp();

    size_t rowm = (size_t)b * NN + m;
    float4 a = make_float4(0.f, 0.f, 0.f, 0.f);
    float a1 = 0.f;
    for (int i = 0; i < cnt; i++) {
        float s = sval[i];
        const float4* hp = (const float4*)(hvec + ((size_t)b * NN + scol[i]) * UU);
        float4 hv = hp[lane];
        a.x = fmaf(s, hv.x, a.x);
        a.y = fmaf(s, hv.y, a.y);
        a.z = fmaf(s, hv.z, a.z);
        a.w = fmaf(s, hv.w, a.w);
        if (lane == 0) a1 = fmaf(s, sinp[g][i], a1);
    }

    // fp32 x1 for pass2
    float* X1 = g_X1f + rowm * 132;
    *(float4*)(X1 + lane * 4) = a;

    __nv_bfloat16* Xh = g_Xhi + rowm * KPAD;
    __nv_bfloat16* Xl = g_Xlo + rowm * KPAD;
    // x0 split (cols 0..127)
    float4 x0 = ((const float4*)(hvec + rowm * UU))[lane];
    split_store4(Xh + lane * 4, Xl + lane * 4, x0);
    // x1 split (cols 132..259)
    split_store4(Xh + 132 + lane * 4, Xl + 132 + lane * 4, a);
    if (lane == 0) {
        X1[128] = a1;
        split_store1pad(Xh + 128, Xl + 128, inp[rowm]);   // x0 inp + pads 129..131
        split_store1pad(Xh + 260, Xl + 260, a1);          // x1 inp + pads 261..263
    }
}

// ---------------- diffusion pass 2: x2 = 2*S@x1 - x0 -------------------------
template <int USE_RH>
__global__ void __launch_bounds__(128) spmm_pass2(
    const float* __restrict__ inp, const float* __restrict__ hparam)
{
    const float* __restrict__ hvec = USE_RH ? (const float*)g_rh : hparam;
    int m = blockIdx.x;
    int g = threadIdx.x >> 5, lane = threadIdx.x & 31;
    int b = blockIdx.y * 4 + g;
    __shared__ int   scol[MAX_NNZ];
    __shared__ float sval[MAX_NNZ];
    __shared__ float sx1i[4][MAX_NNZ];
    int cnt = g_csr_cnt[m];
    if (threadIdx.x < MAX_NNZ) {
        scol[threadIdx.x] = g_csr_col[m * MAX_NNZ + threadIdx.x];
        sval[threadIdx.x] = g_csr_val[m * MAX_NNZ + threadIdx.x];
    }
    __syncthreads();
    if (lane < cnt) sx1i[g][lane] = g_X1f[((size_t)b * NN + scol[lane]) * 132 + 128];
    if (cnt > 32 && lane + 32 < cnt) sx1i[g][lane + 32] = g_X1f[((size_t)b * NN + scol[lane + 32]) * 132 + 128];
    __syncwarp();

    size_t rowm = (size_t)b * NN + m;
    float4 a = make_float4(0.f, 0.f, 0.f, 0.f);
    float a1 = 0.f;
    for (int i = 0; i < cnt; i++) {
        float s = sval[i];
        const float4* xp = (const float4*)(g_X1f + ((size_t)b * NN + scol[i]) * 132);
        float4 hv = xp[lane];
        a.x = fmaf(s, hv.x, a.x);
        a.y = fmaf(s, hv.y, a.y);
        a.z = fmaf(s, hv.z, a.z);
        a.w = fmaf(s, hv.w, a.w);
        if (lane == 0) a1 = fmaf(s, sx1i[g][i], a1);
    }

    float4 x0 = ((const float4*)(hvec + rowm * UU))[lane];
    float4 r;
    r.x = 2.f * a.x - x0.x;
    r.y = 2.f * a.y - x0.y;
    r.z = 2.f * a.z - x0.z;
    r.w = 2.f * a.w - x0.w;

    __nv_bfloat16* Xh = g_Xhi + rowm * KPAD;
    __nv_bfloat16* Xl = g_Xlo + rowm * KPAD;
    split_store4(Xh + 264 + lane * 4, Xl + 264 + lane * 4, r);   // cols 264..391
    if (lane == 0) {
        split_store1pad(Xh + 392, Xl + 392, 2.f * a1 - inp[rowm]);  // 392..395
    }
    if (lane < 5) {   // zero pads 396..415
        uint2 z; z.x = 0u; z.y = 0u;
        *(uint2*)(Xh + 396 + lane * 4) = z;
        *(uint2*)(Xl + 396 + lane * 4) = z;
    }
}

// ---------------- bf16-split tensor-core GEMM --------------------------------
// BM=128 BN=128 BK=16, 256 thr (8 warps 4Mx2N), warp tile 32x64, m16n8k16.
// D = Ah*Bh + Ah*Bl + Al*Bh  (~1e-5 rel err).
// MODE 0: gate (Wgt, N=256, grid.y=2): by0 -> g_rh = sig*h ; by1 -> g_u = sig
// MODE 1: cand (Wct, N=128):           newh = u*h + (1-u)*tanh
template <int MODE>
__global__ void __launch_bounds__(256) gemm_kernel(
    const float* __restrict__ bias, const float* __restrict__ hvec,
    float* __restrict__ newh)
{
    __shared__ __nv_bfloat16 SM[2][4][128 * 24];   // mats: Ah, Al, Bh, Bl (pitch 24)
    const int tid = threadIdx.x;
    const int lane = tid & 31, wid = tid >> 5;
    const int wm = wid >> 1, wn = wid & 1;
    const size_t mbase = (size_t)blockIdx.x * 128;
    const int jb = (MODE == 0) ? blockIdx.y * 128 : 0;

    const __nv_bfloat16* __restrict__ WtH = (MODE == 0) ? g_Wgt_hi : g_Wct_hi;
    const __nv_bfloat16* __restrict__ WtL = (MODE == 0) ? g_Wgt_lo : g_Wct_lo;

    const int lrow = tid >> 1, lhalf = tid & 1;
    const __nv_bfloat16* srcA_h = g_Xhi + (mbase + lrow) * KPAD + lhalf * 8;
    const __nv_bfloat16* srcA_l = g_Xlo + (mbase + lrow) * KPAD + lhalf * 8;
    const __nv_bfloat16* srcB_h = WtH + (size_t)(jb + lrow) * KPAD + lhalf * 8;
    const __nv_bfloat16* srcB_l = WtL + (size_t)(jb + lrow) * KPAD + lhalf * 8;
    const int dsti = lrow * 24 + lhalf * 8;

    float c[2][8][4];
#pragma unroll
    for (int mt = 0; mt < 2; mt++)
#pragma unroll
        for (int j = 0; j < 8; j++)
#pragma unroll
            for (int q = 0; q < 4; q++) c[mt][j][q] = 0.f;

    // preamble: chunk 0 -> buf 0
    {
        cp16(smem_u32(&SM[0][0][dsti]), srcA_h);
        cp16(smem_u32(&SM[0][1][dsti]), srcA_l);
        cp16(smem_u32(&SM[0][2][dsti]), srcB_h);
        cp16(smem_u32(&SM[0][3][dsti]), srcB_l);
        cp_commit();
    }

    const int la = lane & 15;
    const int ka = (lane & 16) ? 8 : 0;
    const int arow = wm * 32 + la;
    const int nb = lane & 7;
    const int kb = (lane & 8) ? 8 : 0;

    for (int t = 0; t < NCH; t++) {
        int cur = t & 1, nxt = cur ^ 1;
        cp_wait0();
        __syncthreads();
        if (t + 1 < NCH) {
            int k0 = (t + 1) * 16;
            cp16(smem_u32(&SM[nxt][0][dsti]), srcA_h + k0);
            cp16(smem_u32(&SM[nxt][1][dsti]), srcA_l + k0);
            cp16(smem_u32(&SM[nxt][2][dsti]), srcB_h + k0);
            cp16(smem_u32(&SM[nxt][3][dsti]), srcB_l + k0);
            cp_commit();
        }

        uint32_t ah[2][4], al[2][4];
#pragma unroll
        for (int mt = 0; mt < 2; mt++) {
            ldsm_x4(ah[mt], smem_u32(&SM[cur][0][(arow + mt * 16) * 24 + ka]));
            ldsm_x4(al[mt], smem_u32(&SM[cur][1][(arow + mt * 16) * 24 + ka]));
        }
#pragma unroll
        for (int j = 0; j < 8; j++) {
            uint32_t bh[2], bl[2];
            int bi = (wn * 64 + j * 8 + nb) * 24 + kb;
            ldsm_x2(bh, smem_u32(&SM[cur][2][bi]));
            ldsm_x2(bl, smem_u32(&SM[cur][3][bi]));
#pragma unroll
            for (int mt = 0; mt < 2; mt++) {
                mma_bf16(c[mt][j], ah[mt], bh);
                mma_bf16(c[mt][j], ah[mt], bl);
                mma_bf16(c[mt][j], al[mt], bh);
            }
        }
    }

    // epilogue
#pragma unroll
    for (int mt = 0; mt < 2; mt++) {
#pragma unroll
        for (int j = 0; j < 8; j++) {
            int row0 = (int)mbase + wm * 32 + mt * 16 + (lane >> 2);
            int col = wn * 64 + j * 8 + (lane & 3) * 2;   // 0..127 in this N-tile
            int jg = jb + col;
            float b0 = bias[jg], b1 = bias[jg + 1];
#pragma unroll
            for (int h2 = 0; h2 < 2; h2++) {
                int row = row0 + h2 * 8;
                float v0 = c[mt][j][h2 * 2 + 0] + b0;
                float v1 = c[mt][j][h2 * 2 + 1] + b1;
                size_t idx = (size_t)row * UU + col;
                if (MODE == 0) {
                    float s0 = 1.f / (1.f + expf(-v0));
                    float s1 = 1.f / (1.f + expf(-v1));
                    if (jb == 0) {
                        float2 hh = *(const float2*)(hvec + idx);
                        float2 o; o.x = s0 * hh.x; o.y = s1 * hh.y;
                        *(float2*)(g_rh + idx) = o;
                    } else {
                        float2 o; o.x = s0; o.y = s1;
                        *(float2*)(g_u + idx) = o;
                    }
                } else {
                    float t0 = tanhf(v0), t1 = tanhf(v1);
                    float2 uu = *(const float2*)(g_u + idx);
                    float2 hh = *(const float2*)(hvec + idx);
                    float2 o;
                    o.x = uu.x * hh.x + (1.f - uu.x) * t0;
                    o.y = uu.y * hh.y + (1.f - uu.y) * t1;
                    *(float2*)(newh + idx) = o;
                }
            }
        }
    }
}

// ---------------- projection -------------------------------------------------
__global__ void proj_kernel(const float* __restrict__ newh,
                            const float* __restrict__ pw,
                            const float* __restrict__ pb,
                            float* __restrict__ out) {
    int gw = (blockIdx.x * blockDim.x + threadIdx.x) >> 5;
    int lane = threadIdx.x & 31;
    if (gw >= MROWS) return;
    float4 v = *(const float4*)(newh + (size_t)gw * UU + lane * 4);
    float4 w = *(const float4*)(pw + lane * 4);
    float d = v.x * w.x + v.y * w.y + v.z * w.z + v.w * w.w;
#pragma unroll
    for (int off = 16; off > 0; off >>= 1)
        d += __shfl_xor_sync(0xffffffffu, d, off);
    if (lane == 0) out[gw] = d + pb[0];
}

// ---------------- launch ------------------------------------------------------
extern "C" void kernel_launch(void* const* d_in, const int* in_sizes, int n_in,
                              void* d_out, int out_size) {
    const float* inp = (const float*)d_in[0];
    const float* h   = (const float*)d_in[1];
    const float* S   = (const float*)d_in[2];
    const float* gw  = (const float*)d_in[3];
    const float* gb  = (const float*)d_in[4];
    const float* cw  = (const float*)d_in[5];
    const float* cb  = (const float*)d_in[6];
    const float* pw  = (const float*)d_in[7];
    const float* pb  = (const float*)d_in[8];
    float* out  = (float*)d_out;
    float* newh = out + MROWS;

    csr_build<<<128, 256>>>(S);
    wtrans<256><<<KPAD, 256>>>(gw);
    wtrans<128><<<KPAD, 128>>>(cw);

    // gate path
    spmm_pass1<0><<<dim3(NN, BB / 4), 128>>>(inp, h);
    spmm_pass2<0><<<dim3(NN, BB / 4), 128>>>(inp, h);
    gemm_kernel<0><<<dim3(MROWS / 128, 2), 256>>>(gb, h, nullptr);

    // cand path
    spmm_pass1<1><<<dim3(NN, BB / 4), 128>>>(inp, nullptr);
    spmm_pass2<1><<<dim3(NN, BB / 4), 128>>>(inp, nullptr);
    gemm_kernel<1><<<dim3(MROWS / 128, 1), 256>>>(cb, h, newh);

    proj_kernel<<<MROWS / 8, 256>>>(newh, pw, pb, out);
}

// round 8
// speedup vs baseline: 2.2463x; 1.0283x over previous
#include <cuda_runtime.h>
#include <cuda_bf16.h>
#include <math.h>
#include <stdint.h>

// Problem constants
#define BB 128
#define NN 1024
#define UU 128
#define NM 3
#define SBLK 132           // per-step block: 128 hvec + 1 inp + 3 pad
#define KPAD 416           // 3*132 = 396 -> 416 (26 x 16)
#define NCH (KPAD / 16)    // 26 k-chunks
#define MROWS 131072
#define MAX_NNZ 64

// Xhi/Xlo row layout (stride KPAD, bf16):
//   [0..127] x0 hvec  [128] x0 inp [129..131] pad
//   [132..259] x1     [260] x1 inp [261..263] pad
//   [264..391] x2     [392] x2 inp [393..415] pad

// ---------------- scratch -----------------------------------------------------
__device__ float         g_X1f[(size_t)MROWS * 132];   // fp32 x1 for pass2 gather
__device__ __nv_bfloat16 g_Xhi[(size_t)MROWS * KPAD];
__device__ __nv_bfloat16 g_Xlo[(size_t)MROWS * KPAD];
__device__ float g_rh[(size_t)MROWS * UU];
__device__ float g_u [(size_t)MROWS * UU];
__device__ __nv_bfloat16 g_Wgt_hi[256 * KPAD];         // gate W^T [N][K]
__device__ __nv_bfloat16 g_Wgt_lo[256 * KPAD];
__device__ __nv_bfloat16 g_Wct_hi[128 * KPAD];         // cand W^T [N][K]
__device__ __nv_bfloat16 g_Wct_lo[128 * KPAD];
__device__ int   g_csr_cnt[NN];
__device__ int   g_csr_col[NN * MAX_NNZ];
__device__ float g_csr_val[NN * MAX_NNZ];

// ---------------- helpers -----------------------------------------------------
__device__ __forceinline__ unsigned smem_u32(const void* p) {
    return (unsigned)__cvta_generic_to_shared(p);
}
__device__ __forceinline__ void cp16(unsigned dst, const void* src) {
    asm volatile("cp.async.cg.shared.global [%0], [%1], 16;" :: "r"(dst), "l"(src));
}
__device__ __forceinline__ void cp_commit() { asm volatile("cp.async.commit_group;"); }
__device__ __forceinline__ void cp_wait0()  { asm volatile("cp.async.wait_group 0;"); }

__device__ __forceinline__ void ldsm_x4(uint32_t* r, uint32_t a) {
    asm volatile("ldmatrix.sync.aligned.m8n8.x4.shared.b16 {%0,%1,%2,%3}, [%4];"
                 : "=r"(r[0]), "=r"(r[1]), "=r"(r[2]), "=r"(r[3]) : "r"(a));
}
__device__ __forceinline__ void ldsm_x2(uint32_t* r, uint32_t a) {
    asm volatile("ldmatrix.sync.aligned.m8n8.x2.shared.b16 {%0,%1}, [%2];"
                 : "=r"(r[0]), "=r"(r[1]) : "r"(a));
}
__device__ __forceinline__ void mma_bf16(float* c, const uint32_t* a, const uint32_t* b) {
    asm volatile("mma.sync.aligned.m16n8k16.row.col.f32.bf16.bf16.f32 "
                 "{%0,%1,%2,%3}, {%4,%5,%6,%7}, {%8,%9}, {%0,%1,%2,%3};"
                 : "+f"(c[0]), "+f"(c[1]), "+f"(c[2]), "+f"(c[3])
                 : "r"(a[0]), "r"(a[1]), "r"(a[2]), "r"(a[3]), "r"(b[0]), "r"(b[1]));
}

__device__ __forceinline__ uint32_t pk2(__nv_bfloat16 a, __nv_bfloat16 b) {
    return (uint32_t)__bfloat16_as_ushort(a) | ((uint32_t)__bfloat16_as_ushort(b) << 16);
}
__device__ __forceinline__ void split_store4(__nv_bfloat16* ph, __nv_bfloat16* pl, float4 v) {
    __nv_bfloat16 h0 = __float2bfloat16(v.x), h1 = __float2bfloat16(v.y),
                  h2 = __float2bfloat16(v.z), h3 = __float2bfloat16(v.w);
    __nv_bfloat16 l0 = __float2bfloat16(v.x - __bfloat162float(h0)),
                  l1 = __float2bfloat16(v.y - __bfloat162float(h1)),
                  l2 = __float2bfloat16(v.z - __bfloat162float(h2)),
                  l3 = __float2bfloat16(v.w - __bfloat162float(h3));
    uint2 uh; uh.x = pk2(h0, h1); uh.y = pk2(h2, h3);
    uint2 ul; ul.x = pk2(l0, l1); ul.y = pk2(l2, l3);
    *(uint2*)ph = uh; *(uint2*)pl = ul;
}
__device__ __forceinline__ void split_store1pad(__nv_bfloat16* ph, __nv_bfloat16* pl, float v) {
    __nv_bfloat16 h = __float2bfloat16(v);
    __nv_bfloat16 l = __float2bfloat16(v - __bfloat162float(h));
    uint2 uh; uh.x = pk2(h, __float2bfloat16(0.f)); uh.y = 0u;
    uint2 ul; ul.x = pk2(l, __float2bfloat16(0.f)); ul.y = 0u;
    *(uint2*)ph = uh; *(uint2*)pl = ul;
}

// 4-way unrolled sparse gather: a += sum_i s_i * src[n_i]   (float4 lanes)
__device__ __forceinline__ void gather_acc(
    const float* __restrict__ base, size_t rowstride, int lane,
    const int* scol, const float* sval, int cnt,
    const float* sextra, float4& a, float& a1, bool lane0)
{
    int i = 0;
    for (; i + 4 <= cnt; i += 4) {
        int n0 = scol[i], n1 = scol[i+1], n2 = scol[i+2], n3 = scol[i+3];
        float s0 = sval[i], s1 = sval[i+1], s2 = sval[i+2], s3 = sval[i+3];
        float4 v0 = *(const float4*)(base + (size_t)n0 * rowstride + lane * 4);
        float4 v1 = *(const float4*)(base + (size_t)n1 * rowstride + lane * 4);
        float4 v2 = *(const float4*)(base + (size_t)n2 * rowstride + lane * 4);
        float4 v3 = *(const float4*)(base + (size_t)n3 * rowstride + lane * 4);
        a.x = fmaf(s0, v0.x, a.x); a.y = fmaf(s0, v0.y, a.y);
        a.z = fmaf(s0, v0.z, a.z); a.w = fmaf(s0, v0.w, a.w);
        a.x = fmaf(s1, v1.x, a.x); a.y = fmaf(s1, v1.y, a.y);
        a.z = fmaf(s1, v1.z, a.z); a.w = fmaf(s1, v1.w, a.w);
        a.x = fmaf(s2, v2.x, a.x); a.y = fmaf(s2, v2.y, a.y);
        a.z = fmaf(s2, v2.z, a.z); a.w = fmaf(s2, v2.w, a.w);
        a.x = fmaf(s3, v3.x, a.x); a.y = fmaf(s3, v3.y, a.y);
        a.z = fmaf(s3, v3.z, a.z); a.w = fmaf(s3, v3.w, a.w);
        if (lane0) {
            a1 = fmaf(s0, sextra[i],   a1);
            a1 = fmaf(s1, sextra[i+1], a1);
            a1 = fmaf(s2, sextra[i+2], a1);
            a1 = fmaf(s3, sextra[i+3], a1);
        }
    }
    for (; i < cnt; i++) {
        float s = sval[i];
        float4 v = *(const float4*)(base + (size_t)scol[i] * rowstride + lane * 4);
        a.x = fmaf(s, v.x, a.x); a.y = fmaf(s, v.y, a.y);
        a.z = fmaf(s, v.z, a.z); a.w = fmaf(s, v.w, a.w);
        if (lane0) a1 = fmaf(s, sextra[i], a1);
    }
}

// ---------------- CSR build ---------------------------------------------------
__global__ void csr_build(const float* __restrict__ S) {
    int w = (blockIdx.x * blockDim.x + threadIdx.x) >> 5;
    int lane = threadIdx.x & 31;
    if (w >= NN) return;
    const float* row = S + (size_t)w * NN;
    int cnt = 0;
    for (int base = 0; base < NN; base += 32) {
        float v = row[base + lane];
        unsigned m = __ballot_sync(0xffffffffu, v != 0.f);
        if (v != 0.f) {
            int pos = cnt + __popc(m & ((1u << lane) - 1u));
            if (pos < MAX_NNZ) {
                g_csr_col[w * MAX_NNZ + pos] = base + lane;
                g_csr_val[w * MAX_NNZ + pos] = v;
            }
        }
        cnt += __popc(m);
    }
    if (lane == 0) g_csr_cnt[w] = cnt < MAX_NNZ ? cnt : MAX_NNZ;
}

// ---------------- weight transpose + bf16 split: -> Wt[n][k] ------------------
template <int LD>
__global__ void wtrans(const float* __restrict__ W) {
    int k = blockIdx.x, j = threadIdx.x;
    int s = k / SBLK, c = k - s * SBLK;
    float v = 0.f;
    if (s < NM && c < 129) {
        int corig = (c == 128) ? 0 : (c + 1);
        v = W[(size_t)(corig * NM + s) * LD + j];
    }
    __nv_bfloat16 hi = __float2bfloat16(v);
    __nv_bfloat16 lo = __float2bfloat16(v - __bfloat162float(hi));
    if (LD == 256) {
        g_Wgt_hi[(size_t)j * KPAD + k] = hi;
        g_Wgt_lo[(size_t)j * KPAD + k] = lo;
    } else {
        g_Wct_hi[(size_t)j * KPAD + k] = hi;
        g_Wct_lo[(size_t)j * KPAD + k] = lo;
    }
}

// ---------------- diffusion pass 1: x0 split + x1 (=S@x0) --------------------
template <int USE_RH>
__global__ void __launch_bounds__(128) spmm_pass1(
    const float* __restrict__ inp, const float* __restrict__ hparam)
{
    const float* __restrict__ hvec = USE_RH ? (const float*)g_rh : hparam;
    int m = blockIdx.x;
    int g = threadIdx.x >> 5, lane = threadIdx.x & 31;
    int b = blockIdx.y * 4 + g;
    __shared__ int   scol[MAX_NNZ];
    __shared__ float sval[MAX_NNZ];
    __shared__ float sinp[4][MAX_NNZ];
    int cnt = g_csr_cnt[m];
    if (threadIdx.x < MAX_NNZ) {
        scol[threadIdx.x] = g_csr_col[m * MAX_NNZ + threadIdx.x];
        sval[threadIdx.x] = g_csr_val[m * MAX_NNZ + threadIdx.x];
    }
    __syncthreads();
    if (lane < cnt) sinp[g][lane] = inp[(size_t)b * NN + scol[lane]];
    if (cnt > 32 && lane + 32 < cnt) sinp[g][lane + 32] = inp[(size_t)b * NN + scol[lane + 32]];
    __syncwarp();

    size_t rowm = (size_t)b * NN + m;
    float4 a = make_float4(0.f, 0.f, 0.f, 0.f);
    float a1 = 0.f;
    gather_acc(hvec + (size_t)b * NN * UU, UU, lane, scol, sval, cnt,
               sinp[g], a, a1, lane == 0);

    // fp32 x1 for pass2
    float* X1 = g_X1f + rowm * 132;
    *(float4*)(X1 + lane * 4) = a;

    __nv_bfloat16* Xh = g_Xhi + rowm * KPAD;
    __nv_bfloat16* Xl = g_Xlo + rowm * KPAD;
    float4 x0 = ((const float4*)(hvec + rowm * UU))[lane];
    split_store4(Xh + lane * 4, Xl + lane * 4, x0);
    split_store4(Xh + 132 + lane * 4, Xl + 132 + lane * 4, a);
    if (lane == 0) {
        X1[128] = a1;
        split_store1pad(Xh + 128, Xl + 128, inp[rowm]);
        split_store1pad(Xh + 260, Xl + 260, a1);
    }
}

// ---------------- diffusion pass 2: x2 = 2*S@x1 - x0 -------------------------
template <int USE_RH>
__global__ void __launch_bounds__(128) spmm_pass2(
    const float* __restrict__ inp, const float* __restrict__ hparam)
{
    const float* __restrict__ hvec = USE_RH ? (const float*)g_rh : hparam;
    int m = blockIdx.x;
    int g = threadIdx.x >> 5, lane = threadIdx.x & 31;
    int b = blockIdx.y * 4 + g;
    __shared__ int   scol[MAX_NNZ];
    __shared__ float sval[MAX_NNZ];
    __shared__ float sx1i[4][MAX_NNZ];
    int cnt = g_csr_cnt[m];
    if (threadIdx.x < MAX_NNZ) {
        scol[threadIdx.x] = g_csr_col[m * MAX_NNZ + threadIdx.x];
        sval[threadIdx.x] = g_csr_val[m * MAX_NNZ + threadIdx.x];
    }
    __syncthreads();
    if (lane < cnt) sx1i[g][lane] = g_X1f[((size_t)b * NN + scol[lane]) * 132 + 128];
    if (cnt > 32 && lane + 32 < cnt) sx1i[g][lane + 32] = g_X1f[((size_t)b * NN + scol[lane + 32]) * 132 + 128];
    __syncwarp();

    size_t rowm = (size_t)b * NN + m;
    float4 a = make_float4(0.f, 0.f, 0.f, 0.f);
    float a1 = 0.f;
    gather_acc(g_X1f + (size_t)b * NN * 132, 132, lane, scol, sval, cnt,
               sx1i[g], a, a1, lane == 0);

    float4 x0 = ((const float4*)(hvec + rowm * UU))[lane];
    float4 r;
    r.x = 2.f * a.x - x0.x;
    r.y = 2.f * a.y - x0.y;
    r.z = 2.f * a.z - x0.z;
    r.w = 2.f * a.w - x0.w;

    __nv_bfloat16* Xh = g_Xhi + rowm * KPAD;
    __nv_bfloat16* Xl = g_Xlo + rowm * KPAD;
    split_store4(Xh + 264 + lane * 4, Xl + 264 + lane * 4, r);
    if (lane == 0) {
        split_store1pad(Xh + 392, Xl + 392, 2.f * a1 - inp[rowm]);
    }
    if (lane < 5) {
        uint2 z; z.x = 0u; z.y = 0u;
        *(uint2*)(Xh + 396 + lane * 4) = z;
        *(uint2*)(Xl + 396 + lane * 4) = z;
    }
}

// ---------------- bf16-split tensor-core GEMM --------------------------------
// BM=128 BN=128 BK=16, 256 thr (8 warps 4Mx2N), warp tile 32x64, m16n8k16.
// D = Ah*Bh + Ah*Bl + Al*Bh.
// smem: one 48KB raw buffer; SM view during mainloop, srow view (aliased)
// for MODE 1 projection reduction AFTER the mainloop (sync-separated).
// MODE 0: gate (Wgt, N=256, grid.y=2): by0 -> g_rh = sig*h ; by1 -> g_u = sig
// MODE 1: cand (Wct, N=128): newh = u*h+(1-u)*tanh ; fused proj -> out
template <int MODE>
__global__ void __launch_bounds__(256) gemm_kernel(
    const float* __restrict__ bias, const float* __restrict__ hvec,
    float* __restrict__ newh, const float* __restrict__ pw,
    const float* __restrict__ pb, float* __restrict__ out)
{
    __shared__ __align__(16) char smem_raw[2 * 4 * 128 * 24 * 2];   // 49152 B
    typedef __nv_bfloat16 (*SMv)[4][128 * 24];
    SMv SM = (SMv)smem_raw;
    float* srow = (float*)smem_raw;            // aliased; used only post-mainloop

    const int tid = threadIdx.x;
    const int lane = tid & 31, wid = tid >> 5;
    const int wm = wid >> 1, wn = wid & 1;
    const size_t mbase = (size_t)blockIdx.x * 128;
    const int jb = (MODE == 0) ? blockIdx.y * 128 : 0;

    const __nv_bfloat16* __restrict__ WtH = (MODE == 0) ? g_Wgt_hi : g_Wct_hi;
    const __nv_bfloat16* __restrict__ WtL = (MODE == 0) ? g_Wgt_lo : g_Wct_lo;

    const int lrow = tid >> 1, lhalf = tid & 1;
    const __nv_bfloat16* srcA_h = g_Xhi + (mbase + lrow) * KPAD + lhalf * 8;
    const __nv_bfloat16* srcA_l = g_Xlo + (mbase + lrow) * KPAD + lhalf * 8;
    const __nv_bfloat16* srcB_h = WtH + (size_t)(jb + lrow) * KPAD + lhalf * 8;
    const __nv_bfloat16* srcB_l = WtL + (size_t)(jb + lrow) * KPAD + lhalf * 8;
    const int dsti = lrow * 24 + lhalf * 8;

    float c[2][8][4];
#pragma unroll
    for (int mt = 0; mt < 2; mt++)
#pragma unroll
        for (int j = 0; j < 8; j++)
#pragma unroll
            for (int q = 0; q < 4; q++) c[mt][j][q] = 0.f;

    {
        cp16(smem_u32(&SM[0][0][dsti]), srcA_h);
        cp16(smem_u32(&SM[0][1][dsti]), srcA_l);
        cp16(smem_u32(&SM[0][2][dsti]), srcB_h);
        cp16(smem_u32(&SM[0][3][dsti]), srcB_l);
        cp_commit();
    }

    const int la = lane & 15;
    const int ka = (lane & 16) ? 8 : 0;
    const int arow = wm * 32 + la;
    const int nb = lane & 7;
    const int kb = (lane & 8) ? 8 : 0;

    for (int t = 0; t < NCH; t++) {
        int cur = t & 1, nxt = cur ^ 1;
        cp_wait0();
        __syncthreads();
        if (t + 1 < NCH) {
            int k0 = (t + 1) * 16;
            cp16(smem_u32(&SM[nxt][0][dsti]), srcA_h + k0);
            cp16(smem_u32(&SM[nxt][1][dsti]), srcA_l + k0);
            cp16(smem_u32(&SM[nxt][2][dsti]), srcB_h + k0);
            cp16(smem_u32(&SM[nxt][3][dsti]), srcB_l + k0);
            cp_commit();
        }

        uint32_t ah[2][4], al[2][4];
#pragma unroll
        for (int mt = 0; mt < 2; mt++) {
            ldsm_x4(ah[mt], smem_u32(&SM[cur][0][(arow + mt * 16) * 24 + ka]));
            ldsm_x4(al[mt], smem_u32(&SM[cur][1][(arow + mt * 16) * 24 + ka]));
        }
#pragma unroll
        for (int j = 0; j < 8; j++) {
            uint32_t bh[2], bl[2];
            int bi = (wn * 64 + j * 8 + nb) * 24 + kb;
            ldsm_x2(bh, smem_u32(&SM[cur][2][bi]));
            ldsm_x2(bl, smem_u32(&SM[cur][3][bi]));
#pragma unroll
            for (int mt = 0; mt < 2; mt++) {
                mma_bf16(c[mt][j], ah[mt], bh);
                mma_bf16(c[mt][j], ah[mt], bl);
                mma_bf16(c[mt][j], al[mt], bh);
            }
        }
    }

    // epilogue
    float part[2][2];   // proj partials per (mt, h2) row
    if (MODE == 1) { part[0][0] = part[0][1] = part[1][0] = part[1][1] = 0.f; }

#pragma unroll
    for (int mt = 0; mt < 2; mt++) {
#pragma unroll
        for (int j = 0; j < 8; j++) {
            int row0 = (int)mbase + wm * 32 + mt * 16 + (lane >> 2);
            int col = wn * 64 + j * 8 + (lane & 3) * 2;
            int jg = jb + col;
            float b0 = bias[jg], b1 = bias[jg + 1];
#pragma unroll
            for (int h2 = 0; h2 < 2; h2++) {
                int row = row0 + h2 * 8;
                float v0 = c[mt][j][h2 * 2 + 0] + b0;
                float v1 = c[mt][j][h2 * 2 + 1] + b1;
                size_t idx = (size_t)row * UU + col;
                if (MODE == 0) {
                    float s0 = 1.f / (1.f + expf(-v0));
                    float s1 = 1.f / (1.f + expf(-v1));
                    if (jb == 0) {
                        float2 hh = *(const float2*)(hvec + idx);
                        float2 o; o.x = s0 * hh.x; o.y = s1 * hh.y;
                        *(float2*)(g_rh + idx) = o;
                    } else {
                        float2 o; o.x = s0; o.y = s1;
                        *(float2*)(g_u + idx) = o;
                    }
                } else {
                    float t0 = tanhf(v0), t1 = tanhf(v1);
                    float2 uu = *(const float2*)(g_u + idx);
                    float2 hh = *(const float2*)(hvec + idx);
                    float2 o;
                    o.x = uu.x * hh.x + (1.f - uu.x) * t0;
                    o.y = uu.y * hh.y + (1.f - uu.y) * t1;
                    *(float2*)(newh + idx) = o;
                    part[mt][h2] = fmaf(o.x, pw[col], part[mt][h2]);
                    part[mt][h2] = fmaf(o.y, pw[col + 1], part[mt][h2]);
                }
            }
        }
    }

    if (MODE == 1) {
        __syncthreads();               // all SM reads done; safe to alias srow
        if (tid < 128) srow[tid] = 0.f;
        __syncthreads();
#pragma unroll
        for (int mt = 0; mt < 2; mt++)
#pragma unroll
            for (int h2 = 0; h2 < 2; h2++) {
                int lr = wm * 32 + mt * 16 + h2 * 8 + (lane >> 2);
                atomicAdd(&srow[lr], part[mt][h2]);
            }
        __syncthreads();
        if (tid < 128) out[mbase + tid] = srow[tid] + pb[0];
    }
}

// ---------------- launch ------------------------------------------------------
extern "C" void kernel_launch(void* const* d_in, const int* in_sizes, int n_in,
                              void* d_out, int out_size) {
    const float* inp = (const float*)d_in[0];
    const float* h   = (const float*)d_in[1];
    const float* S   = (const float*)d_in[2];
    const float* gw  = (const float*)d_in[3];
    const float* gb  = (const float*)d_in[4];
    const float* cw  = (const float*)d_in[5];
    const float* cb  = (const float*)d_in[6];
    const float* pw  = (const float*)d_in[7];
    const float* pb  = (const float*)d_in[8];
    float* out  = (float*)d_out;
    float* newh = out + MROWS;

    csr_build<<<128, 256>>>(S);
    wtrans<256><<<KPAD, 256>>>(gw);
    wtrans<128><<<KPAD, 128>>>(cw);

    // gate path
    spmm_pass1<0><<<dim3(NN, BB / 4), 128>>>(inp, h);
    spmm_pass2<0><<<dim3(NN, BB / 4), 128>>>(inp, h);
    gemm_kernel<0><<<dim3(MROWS / 128, 2), 256>>>(gb, h, nullptr, nullptr, nullptr, nullptr);

    // cand path (projection fused into epilogue)
    spmm_pass1<1><<<dim3(NN, BB / 4), 128>>>(inp, nullptr);
    spmm_pass2<1><<<dim3(NN, BB / 4), 128>>>(inp, nullptr);
    gemm_kernel<1><<<dim3(MROWS / 128, 1), 256>>>(cb, h, newh, pw, pb, out);
}

// round 11
// speedup vs baseline: 2.9290x; 1.3039x over previous
#include <cuda_runtime.h>
#include <cuda_fp16.h>
#include <math.h>
#include <stdint.h>

// Problem constants
#define BB 128
#define NN 1024
#define UU 128
#define NM 3
#define SBLK 132           // per-step block: 128 hvec + 1 inp + 3 pad
#define KPAD 416           // 3*132 = 396 -> 416 (26 x 16)
#define NCH (KPAD / 16)    // 26 k-chunks
#define MROWS 131072
#define MAX_NNZ 64

// g_Xh row layout (stride KPAD, fp16):
//   [0..127] x0 hvec  [128] x0 inp [129..131] pad
//   [132..259] x1     [260] x1 inp [261..263] pad
//   [264..391] x2     [392] x2 inp [393..415] pad

// ---------------- scratch -----------------------------------------------------
__device__ float  g_X1f[(size_t)MROWS * 132];   // fp32 x1 for pass2 gather
__device__ __half g_Xh[(size_t)MROWS * KPAD];   // fp16 Xcat (A operand)
__device__ float  g_rh[(size_t)MROWS * UU];
__device__ float  g_u [(size_t)MROWS * UU];
__device__ __half g_Wgt[256 * KPAD];            // gate W^T [N][K] fp16
__device__ __half g_Wct[128 * KPAD];            // cand W^T [N][K] fp16
__device__ int    g_csr_cnt[NN];
__device__ int    g_csr_col[NN * MAX_NNZ];
__device__ float  g_csr_val[NN * MAX_NNZ];

// ---------------- helpers -----------------------------------------------------
__device__ __forceinline__ unsigned smem_u32(const void* p) {
    return (unsigned)__cvta_generic_to_shared(p);
}
__device__ __forceinline__ void cp16(unsigned dst, const void* src) {
    asm volatile("cp.async.cg.shared.global [%0], [%1], 16;" :: "r"(dst), "l"(src));
}
__device__ __forceinline__ void cp_commit() { asm volatile("cp.async.commit_group;"); }
__device__ __forceinline__ void cp_wait0()  { asm volatile("cp.async.wait_group 0;"); }

__device__ __forceinline__ void ldsm_x4(uint32_t* r, uint32_t a) {
    asm volatile("ldmatrix.sync.aligned.m8n8.x4.shared.b16 {%0,%1,%2,%3}, [%4];"
                 : "=r"(r[0]), "=r"(r[1]), "=r"(r[2]), "=r"(r[3]) : "r"(a));
}
__device__ __forceinline__ void ldsm_x2(uint32_t* r, uint32_t a) {
    asm volatile("ldmatrix.sync.aligned.m8n8.x2.shared.b16 {%0,%1}, [%2];"
                 : "=r"(r[0]), "=r"(r[1]) : "r"(a));
}
__device__ __forceinline__ void mma_f16(float* c, const uint32_t* a, const uint32_t* b) {
    asm volatile("mma.sync.aligned.m16n8k16.row.col.f32.f16.f16.f32 "
                 "{%0,%1,%2,%3}, {%4,%5,%6,%7}, {%8,%9}, {%0,%1,%2,%3};"
                 : "+f"(c[0]), "+f"(c[1]), "+f"(c[2]), "+f"(c[3])
                 : "r"(a[0]), "r"(a[1]), "r"(a[2]), "r"(a[3]), "r"(b[0]), "r"(b[1]));
}

__device__ __forceinline__ void h_store4(__half* p, float4 v) {
    __half2 h01 = __floats2half2_rn(v.x, v.y);
    __half2 h23 = __floats2half2_rn(v.z, v.w);
    uint2 u; u.x = *(uint32_t*)&h01; u.y = *(uint32_t*)&h23;
    *(uint2*)p = u;
}
__device__ __forceinline__ void h_store1pad(__half* p, float v) {
    __half2 h = __floats2half2_rn(v, 0.f);
    uint2 u; u.x = *(uint32_t*)&h; u.y = 0u;
    *(uint2*)p = u;
}

// 4-way unrolled sparse gather: a += sum_i s_i * src[n_i]   (float4 lanes)
__device__ __forceinline__ void gather_acc(
    const float* __restrict__ base, size_t rowstride, int lane,
    const int* scol, const float* sval, int cnt,
    const float* sextra, float4& a, float& a1, bool lane0)
{
    int i = 0;
    for (; i + 4 <= cnt; i += 4) {
        int n0 = scol[i], n1 = scol[i+1], n2 = scol[i+2], n3 = scol[i+3];
        float s0 = sval[i], s1 = sval[i+1], s2 = sval[i+2], s3 = sval[i+3];
        float4 v0 = *(const float4*)(base + (size_t)n0 * rowstride + lane * 4);
        float4 v1 = *(const float4*)(base + (size_t)n1 * rowstride + lane * 4);
        float4 v2 = *(const float4*)(base + (size_t)n2 * rowstride + lane * 4);
        float4 v3 = *(const float4*)(base + (size_t)n3 * rowstride + lane * 4);
        a.x = fmaf(s0, v0.x, a.x); a.y = fmaf(s0, v0.y, a.y);
        a.z = fmaf(s0, v0.z, a.z); a.w = fmaf(s0, v0.w, a.w);
        a.x = fmaf(s1, v1.x, a.x); a.y = fmaf(s1, v1.y, a.y);
        a.z = fmaf(s1, v1.z, a.z); a.w = fmaf(s1, v1.w, a.w);
        a.x = fmaf(s2, v2.x, a.x); a.y = fmaf(s2, v2.y, a.y);
        a.z = fmaf(s2, v2.z, a.z); a.w = fmaf(s2, v2.w, a.w);
        a.x = fmaf(s3, v3.x, a.x); a.y = fmaf(s3, v3.y, a.y);
        a.z = fmaf(s3, v3.z, a.z); a.w = fmaf(s3, v3.w, a.w);
        if (lane0) {
            a1 = fmaf(s0, sextra[i],   a1);
            a1 = fmaf(s1, sextra[i+1], a1);
            a1 = fmaf(s2, sextra[i+2], a1);
            a1 = fmaf(s3, sextra[i+3], a1);
        }
    }
    for (; i < cnt; i++) {
        float s = sval[i];
        float4 v = *(const float4*)(base + (size_t)scol[i] * rowstride + lane * 4);
        a.x = fmaf(s, v.x, a.x); a.y = fmaf(s, v.y, a.y);
        a.z = fmaf(s, v.z, a.z); a.w = fmaf(s, v.w, a.w);
        if (lane0) a1 = fmaf(s, sextra[i], a1);
    }
}

// ---------------- CSR build ---------------------------------------------------
__global__ void csr_build(const float* __restrict__ S) {
    int w = (blockIdx.x * blockDim.x + threadIdx.x) >> 5;
    int lane = threadIdx.x & 31;
    if (w >= NN) return;
    const float* row = S + (size_t)w * NN;
    int cnt = 0;
    for (int base = 0; base < NN; base += 32) {
        float v = row[base + lane];
        unsigned m = __ballot_sync(0xffffffffu, v != 0.f);
        if (v != 0.f) {
            int pos = cnt + __popc(m & ((1u << lane) - 1u));
            if (pos < MAX_NNZ) {
                g_csr_col[w * MAX_NNZ + pos] = base + lane;
                g_csr_val[w * MAX_NNZ + pos] = v;
            }
        }
        cnt += __popc(m);
    }
    if (lane == 0) g_csr_cnt[w] = cnt < MAX_NNZ ? cnt : MAX_NNZ;
}

// ---------------- weight transpose to fp16 -> Wt[n][k] ------------------------
// ref k = c_orig*NM + s (c_orig 0 = inp, 1..128 = hvec); new k = s*SBLK + c_new.
template <int LD>
__global__ void wtrans(const float* __restrict__ W) {
    int k = blockIdx.x, j = threadIdx.x;
    int s = k / SBLK, c = k - s * SBLK;
    float v = 0.f;
    if (s < NM && c < 129) {
        int corig = (c == 128) ? 0 : (c + 1);
        v = W[(size_t)(corig * NM + s) * LD + j];
    }
    __half hv = __float2half_rn(v);
    if (LD == 256) g_Wgt[(size_t)j * KPAD + k] = hv;
    else           g_Wct[(size_t)j * KPAD + k] = hv;
}

// ---------------- diffusion pass 1: x0 + x1 (=S@x0) ---------------------------
template <int USE_RH>
__global__ void __launch_bounds__(128) spmm_pass1(
    const float* __restrict__ inp, const float* __restrict__ hparam)
{
    const float* __restrict__ hvec = USE_RH ? (const float*)g_rh : hparam;
    int m = blockIdx.x;
    int g = threadIdx.x >> 5, lane = threadIdx.x & 31;
    int b = blockIdx.y * 4 + g;
    __shared__ int   scol[MAX_NNZ];
    __shared__ float sval[MAX_NNZ];
    __shared__ float sinp[4][MAX_NNZ];
    int cnt = g_csr_cnt[m];
    if (threadIdx.x < MAX_NNZ) {
        scol[threadIdx.x] = g_csr_col[m * MAX_NNZ + threadIdx.x];
        sval[threadIdx.x] = g_csr_val[m * MAX_NNZ + threadIdx.x];
    }
    __syncthreads();
    if (lane < cnt) sinp[g][lane] = inp[(size_t)b * NN + scol[lane]];
    if (cnt > 32 && lane + 32 < cnt) sinp[g][lane + 32] = inp[(size_t)b * NN + scol[lane + 32]];
    __syncwarp();

    size_t rowm = (size_t)b * NN + m;
    float4 a = make_float4(0.f, 0.f, 0.f, 0.f);
    float a1 = 0.f;
    gather_acc(hvec + (size_t)b * NN * UU, UU, lane, scol, sval, cnt,
               sinp[g], a, a1, lane == 0);

    // fp32 x1 for pass2
    float* X1 = g_X1f + rowm * 132;
    *(float4*)(X1 + lane * 4) = a;

    __half* Xh = g_Xh + rowm * KPAD;
    float4 x0 = ((const float4*)(hvec + rowm * UU))[lane];
    h_store4(Xh + lane * 4, x0);            // x0 (cols 0..127)
    h_store4(Xh + 132 + lane * 4, a);       // x1 (cols 132..259)
    if (lane == 0) {
        X1[128] = a1;
        h_store1pad(Xh + 128, inp[rowm]);   // x0 inp + pads 129..131
        h_store1pad(Xh + 260, a1);          // x1 inp + pads 261..263
    }
}

// ---------------- diffusion pass 2: x2 = 2*S@x1 - x0 --------------------------
template <int USE_RH>
__global__ void __launch_bounds__(128) spmm_pass2(
    const float* __restrict__ inp, const float* __restrict__ hparam)
{
    const float* __restrict__ hvec = USE_RH ? (const float*)g_rh : hparam;
    int m = blockIdx.x;
    int g = threadIdx.x >> 5, lane = threadIdx.x & 31;
    int b = blockIdx.y * 4 + g;
    __shared__ int   scol[MAX_NNZ];
    __shared__ float sval[MAX_NNZ];
    __shared__ float sx1i[4][MAX_NNZ];
    int cnt = g_csr_cnt[m];
    if (threadIdx.x < MAX_NNZ) {
        scol[threadIdx.x] = g_csr_col[m * MAX_NNZ + threadIdx.x];
        sval[threadIdx.x] = g_csr_val[m * MAX_NNZ + threadIdx.x];
    }
    __syncthreads();
    if (lane < cnt) sx1i[g][lane] = g_X1f[((size_t)b * NN + scol[lane]) * 132 + 128];
    if (cnt > 32 && lane + 32 < cnt) sx1i[g][lane + 32] = g_X1f[((size_t)b * NN + scol[lane + 32]) * 132 + 128];
    __syncwarp();

    size_t rowm = (size_t)b * NN + m;
    float4 a = make_float4(0.f, 0.f, 0.f, 0.f);
    float a1 = 0.f;
    gather_acc(g_X1f + (size_t)b * NN * 132, 132, lane, scol, sval, cnt,
               sx1i[g], a, a1, lane == 0);

    float4 x0 = ((const float4*)(hvec + rowm * UU))[lane];
    float4 r;
    r.x = 2.f * a.x - x0.x;
    r.y = 2.f * a.y - x0.y;
    r.z = 2.f * a.z - x0.z;
    r.w = 2.f * a.w - x0.w;

    __half* Xh = g_Xh + rowm * KPAD;
    h_store4(Xh + 264 + lane * 4, r);                     // cols 264..391
    if (lane == 0) h_store1pad(Xh + 392, 2.f * a1 - inp[rowm]);   // 392..395
    if (lane < 5) {                                       // zero pads 396..415
        uint2 z; z.x = 0u; z.y = 0u;
        *(uint2*)(Xh + 396 + lane * 4) = z;
    }
}

// ---------------- fp16 tensor-core GEMM ---------------------------------------
// BM=128 BN=128 BK=16, 256 thr (8 warps 4Mx2N), warp tile 32x64, m16n8k16.
// Single product (fp16 inputs, fp32 accum): rel_err ~2-5e-4 vs 1e-3 budget.
// smem: one raw buffer; SM view during mainloop, srow (aliased) after.
// MODE 0: gate (Wgt, N=256, grid.y=2): by0 -> g_rh = sig*h ; by1 -> g_u = sig
// MODE 1: cand (Wct, N=128): newh = u*h+(1-u)*tanh ; fused proj -> out
template <int MODE>
__global__ void __launch_bounds__(256) gemm_kernel(
    const float* __restrict__ bias, const float* __restrict__ hvec,
    float* __restrict__ newh, const float* __restrict__ pw,
    const float* __restrict__ pb, float* __restrict__ out)
{
    __shared__ __align__(16) char smem_raw[2 * 2 * 128 * 24 * 2];   // 24576 B
    typedef __half (*SMv)[2][128 * 24];
    SMv SM = (SMv)smem_raw;
    float* srow = (float*)smem_raw;            // aliased; post-mainloop only

    const int tid = threadIdx.x;
    const int lane = tid & 31, wid = tid >> 5;
    const int wm = wid >> 1, wn = wid & 1;
    const size_t mbase = (size_t)blockIdx.x * 128;
    const int jb = (MODE == 0) ? blockIdx.y * 128 : 0;

    const __half* __restrict__ Wt = (MODE == 0) ? g_Wgt : g_Wct;

    const int lrow = tid >> 1, lhalf = tid & 1;
    const __half* srcA = g_Xh + (mbase + lrow) * KPAD + lhalf * 8;
    const __half* srcB = Wt + (size_t)(jb + lrow) * KPAD + lhalf * 8;
    const int dsti = lrow * 24 + lhalf * 8;

    float c[2][8][4];
#pragma unroll
    for (int mt = 0; mt < 2; mt++)
#pragma unroll
        for (int j = 0; j < 8; j++)
#pragma unroll
            for (int q = 0; q < 4; q++) c[mt][j][q] = 0.f;

    {
        cp16(smem_u32(&SM[0][0][dsti]), srcA);
        cp16(smem_u32(&SM[0][1][dsti]), srcB);
        cp_commit();
    }

    const int la = lane & 15;
    const int ka = (lane & 16) ? 8 : 0;
    const int arow = wm * 32 + la;
    const int nb = lane & 7;
    const int kb = (lane & 8) ? 8 : 0;

    for (int t = 0; t < NCH; t++) {
        int cur = t & 1, nxt = cur ^ 1;
        cp_wait0();
        __syncthreads();
        if (t + 1 < NCH) {
            int k0 = (t + 1) * 16;
            cp16(smem_u32(&SM[nxt][0][dsti]), srcA + k0);
            cp16(smem_u32(&SM[nxt][1][dsti]), srcB + k0);
            cp_commit();
        }

        uint32_t ah[2][4];
#pragma unroll
        for (int mt = 0; mt < 2; mt++)
            ldsm_x4(ah[mt], smem_u32(&SM[cur][0][(arow + mt * 16) * 24 + ka]));
#pragma unroll
        for (int j = 0; j < 8; j++) {
            uint32_t bh[2];
            int bi = (wn * 64 + j * 8 + nb) * 24 + kb;
            ldsm_x2(bh, smem_u32(&SM[cur][1][bi]));
#pragma unroll
            for (int mt = 0; mt < 2; mt++)
                mma_f16(c[mt][j], ah[mt], bh);
        }
    }

    // epilogue
    float part[2][2];
    if (MODE == 1) { part[0][0] = part[0][1] = part[1][0] = part[1][1] = 0.f; }

#pragma unroll
    for (int mt = 0; mt < 2; mt++) {
#pragma unroll
        for (int j = 0; j < 8; j++) {
            int row0 = (int)mbase + wm * 32 + mt * 16 + (lane >> 2);
            int col = wn * 64 + j * 8 + (lane & 3) * 2;
            int jg = jb + col;
            float b0 = bias[jg], b1 = bias[jg + 1];
#pragma unroll
            for (int h2 = 0; h2 < 2; h2++) {
                int row = row0 + h2 * 8;
                float v0 = c[mt][j][h2 * 2 + 0] + b0;
                float v1 = c[mt][j][h2 * 2 + 1] + b1;
                size_t idx = (size_t)row * UU + col;
                if (MODE == 0) {
                    float s0 = 1.f / (1.f + expf(-v0));
                    float s1 = 1.f / (1.f + expf(-v1));
                    if (jb == 0) {
                        float2 hh = *(const float2*)(hvec + idx);
                        float2 o; o.x = s0 * hh.x; o.y = s1 * hh.y;
                        *(float2*)(g_rh + idx) = o;
                    } else {
                        float2 o; o.x = s0; o.y = s1;
                        *(float2*)(g_u + idx) = o;
                    }
                } else {
                    float t0 = tanhf(v0), t1 = tanhf(v1);
                    float2 uu = *(const float2*)(g_u + idx);
                    float2 hh = *(const float2*)(hvec + idx);
                    float2 o;
                    o.x = uu.x * hh.x + (1.f - uu.x) * t0;
                    o.y = uu.y * hh.y + (1.f - uu.y) * t1;
                    *(float2*)(newh + idx) = o;
                    part[mt][h2] = fmaf(o.x, pw[col], part[mt][h2]);
                    part[mt][h2] = fmaf(o.y, pw[col + 1], part[mt][h2]);
                }
            }
        }
    }

    if (MODE == 1) {
        __syncthreads();               // SM reads done; safe to alias srow
        if (tid < 128) srow[tid] = 0.f;
        __syncthreads();
#pragma unroll
        for (int mt = 0; mt < 2; mt++)
#pragma unroll
            for (int h2 = 0; h2 < 2; h2++) {
                int lr = wm * 32 + mt * 16 + h2 * 8 + (lane >> 2);
                atomicAdd(&srow[lr], part[mt][h2]);
            }
        __syncthreads();
        if (tid < 128) out[mbase + tid] = srow[tid] + pb[0];
    }
}

// ---------------- launch ------------------------------------------------------
extern "C" void kernel_launch(void* const* d_in, const int* in_sizes, int n_in,
                              void* d_out, int out_size) {
    const float* inp = (const float*)d_in[0];
    const float* h   = (const float*)d_in[1];
    const float* S   = (const float*)d_in[2];
    const float* gw  = (const float*)d_in[3];
    const float* gb  = (const float*)d_in[4];
    const float* cw  = (const float*)d_in[5];
    const float* cb  = (const float*)d_in[6];
    const float* pw  = (const float*)d_in[7];
    const float* pb  = (const float*)d_in[8];
    float* out  = (float*)d_out;
    float* newh = out + MROWS;

    csr_build<<<128, 256>>>(S);
    wtrans<256><<<KPAD, 256>>>(gw);
    wtrans<128><<<KPAD, 128>>>(cw);

    // gate path
    spmm_pass1<0><<<dim3(NN, BB / 4), 128>>>(inp, h);
    spmm_pass2<0><<<dim3(NN, BB / 4), 128>>>(inp, h);
    gemm_kernel<0><<<dim3(MROWS / 128, 2), 256>>>(gb, h, nullptr, nullptr, nullptr, nullptr);

    // cand path (projection fused)
    spmm_pass1<1><<<dim3(NN, BB / 4), 128>>>(inp, nullptr);
    spmm_pass2<1><<<dim3(NN, BB / 4), 128>>>(inp, nullptr);
    gemm_kernel<1><<<dim3(MROWS / 128, 1), 256>>>(cb, h, newh, pw, pb, out);
}

// round 12
// speedup vs baseline: 3.0412x; 1.0383x over previous
#include <cuda_runtime.h>
#include <cuda_fp16.h>
#include <math.h>
#include <stdint.h>

// Problem constants
#define BB 128
#define NN 1024
#define UU 128
#define NM 3
#define SBLK 132           // per-step block: 128 hvec + 1 inp + 3 pad
#define KPAD 416           // 3*132 = 396 -> 416 (26 x 16)
#define NCH (KPAD / 16)    // 26 k-chunks
#define MROWS 131072
#define MAX_NNZ 64

// g_Xh row layout (stride KPAD, fp16):
//   [0..127] x0 hvec  [128] x0 inp [129..131] pad
//   [132..259] x1     [260] x1 inp [261..263] pad
//   [264..391] x2     [392] x2 inp [393..415] pad

// ---------------- scratch -----------------------------------------------------
__device__ __half g_h16[(size_t)MROWS * UU];    // fp16 copy of h input
__device__ __half g_Xh[(size_t)MROWS * KPAD];   // fp16 Xcat (A operand)
__device__ __half g_rh[(size_t)MROWS * UU];     // r*h (fp16)
__device__ float  g_u [(size_t)MROWS * UU];
__device__ __half g_Wgt[256 * KPAD];            // gate W^T [N][K] fp16
__device__ __half g_Wct[128 * KPAD];            // cand W^T [N][K] fp16
__device__ int    g_csr_cnt[NN];
__device__ int    g_csr_col[NN * MAX_NNZ];
__device__ float  g_csr_val[NN * MAX_NNZ];

// ---------------- helpers -----------------------------------------------------
__device__ __forceinline__ unsigned smem_u32(const void* p) {
    return (unsigned)__cvta_generic_to_shared(p);
}
__device__ __forceinline__ void cp16(unsigned dst, const void* src) {
    asm volatile("cp.async.cg.shared.global [%0], [%1], 16;" :: "r"(dst), "l"(src));
}
__device__ __forceinline__ void cp_commit() { asm volatile("cp.async.commit_group;"); }
__device__ __forceinline__ void cp_wait0()  { asm volatile("cp.async.wait_group 0;"); }

__device__ __forceinline__ void ldsm_x4(uint32_t* r, uint32_t a) {
    asm volatile("ldmatrix.sync.aligned.m8n8.x4.shared.b16 {%0,%1,%2,%3}, [%4];"
                 : "=r"(r[0]), "=r"(r[1]), "=r"(r[2]), "=r"(r[3]) : "r"(a));
}
__device__ __forceinline__ void ldsm_x2(uint32_t* r, uint32_t a) {
    asm volatile("ldmatrix.sync.aligned.m8n8.x2.shared.b16 {%0,%1}, [%2];"
                 : "=r"(r[0]), "=r"(r[1]) : "r"(a));
}
__device__ __forceinline__ void mma_f16(float* c, const uint32_t* a, const uint32_t* b) {
    asm volatile("mma.sync.aligned.m16n8k16.row.col.f32.f16.f16.f32 "
                 "{%0,%1,%2,%3}, {%4,%5,%6,%7}, {%8,%9}, {%0,%1,%2,%3};"
                 : "+f"(c[0]), "+f"(c[1]), "+f"(c[2]), "+f"(c[3])
                 : "r"(a[0]), "r"(a[1]), "r"(a[2]), "r"(a[3]), "r"(b[0]), "r"(b[1]));
}

__device__ __forceinline__ void h_store4(__half* p, float4 v) {
    __half2 h01 = __floats2half2_rn(v.x, v.y);
    __half2 h23 = __floats2half2_rn(v.z, v.w);
    uint2 u; u.x = *(uint32_t*)&h01; u.y = *(uint32_t*)&h23;
    *(uint2*)p = u;
}
__device__ __forceinline__ void h_store1pad(__half* p, float v) {
    __half2 h = __floats2half2_rn(v, 0.f);
    uint2 u; u.x = *(uint32_t*)&h; u.y = 0u;
    *(uint2*)p = u;
}
__device__ __forceinline__ float4 h_load4(const __half* p) {
    uint2 u = *(const uint2*)p;
    __half2 p01 = *(__half2*)&u.x, p23 = *(__half2*)&u.y;
    float2 f01 = __half22float2(p01), f23 = __half22float2(p23);
    return make_float4(f01.x, f01.y, f23.x, f23.y);
}

// 4-way unrolled fp16 sparse gather: a += sum_i s_i * src[n_i]  (4 ch / lane)
__device__ __forceinline__ void gather_acc_h(
    const __half* __restrict__ base, size_t rowstride, int lane,
    const int* scol, const float* sval, int cnt,
    const float* sextra, float4& a, float& a1, bool lane0)
{
    int i = 0;
    for (; i + 4 <= cnt; i += 4) {
        int n0 = scol[i], n1 = scol[i+1], n2 = scol[i+2], n3 = scol[i+3];
        float s0 = sval[i], s1 = sval[i+1], s2 = sval[i+2], s3 = sval[i+3];
        float4 v0 = h_load4(base + (size_t)n0 * rowstride + lane * 4);
        float4 v1 = h_load4(base + (size_t)n1 * rowstride + lane * 4);
        float4 v2 = h_load4(base + (size_t)n2 * rowstride + lane * 4);
        float4 v3 = h_load4(base + (size_t)n3 * rowstride + lane * 4);
        a.x = fmaf(s0, v0.x, a.x); a.y = fmaf(s0, v0.y, a.y);
        a.z = fmaf(s0, v0.z, a.z); a.w = fmaf(s0, v0.w, a.w);
        a.x = fmaf(s1, v1.x, a.x); a.y = fmaf(s1, v1.y, a.y);
        a.z = fmaf(s1, v1.z, a.z); a.w = fmaf(s1, v1.w, a.w);
        a.x = fmaf(s2, v2.x, a.x); a.y = fmaf(s2, v2.y, a.y);
        a.z = fmaf(s2, v2.z, a.z); a.w = fmaf(s2, v2.w, a.w);
        a.x = fmaf(s3, v3.x, a.x); a.y = fmaf(s3, v3.y, a.y);
        a.z = fmaf(s3, v3.z, a.z); a.w = fmaf(s3, v3.w, a.w);
        if (lane0) {
            a1 = fmaf(s0, sextra[i],   a1);
            a1 = fmaf(s1, sextra[i+1], a1);
            a1 = fmaf(s2, sextra[i+2], a1);
            a1 = fmaf(s3, sextra[i+3], a1);
        }
    }
    for (; i < cnt; i++) {
        float s = sval[i];
        float4 v = h_load4(base + (size_t)scol[i] * rowstride + lane * 4);
        a.x = fmaf(s, v.x, a.x); a.y = fmaf(s, v.y, a.y);
        a.z = fmaf(s, v.z, a.z); a.w = fmaf(s, v.w, a.w);
        if (lane0) a1 = fmaf(s, sextra[i], a1);
    }
}

// ---------------- h -> fp16 conversion ----------------------------------------
__global__ void h2half(const float* __restrict__ h) {
    size_t i = (size_t)blockIdx.x * 256 + threadIdx.x;   // 4 floats / thread
    float4 v = *(const float4*)(h + i * 4);
    h_store4(g_h16 + i * 4, v);
}

// ---------------- CSR build ---------------------------------------------------
__global__ void csr_build(const float* __restrict__ S) {
    int w = (blockIdx.x * blockDim.x + threadIdx.x) >> 5;
    int lane = threadIdx.x & 31;
    if (w >= NN) return;
    const float* row = S + (size_t)w * NN;
    int cnt = 0;
    for (int base = 0; base < NN; base += 32) {
        float v = row[base + lane];
        unsigned m = __ballot_sync(0xffffffffu, v != 0.f);
        if (v != 0.f) {
            int pos = cnt + __popc(m & ((1u << lane) - 1u));
            if (pos < MAX_NNZ) {
                g_csr_col[w * MAX_NNZ + pos] = base + lane;
                g_csr_val[w * MAX_NNZ + pos] = v;
            }
        }
        cnt += __popc(m);
    }
    if (lane == 0) g_csr_cnt[w] = cnt < MAX_NNZ ? cnt : MAX_NNZ;
}

// ---------------- weight transpose to fp16 -> Wt[n][k] ------------------------
template <int LD>
__global__ void wtrans(const float* __restrict__ W) {
    int k = blockIdx.x, j = threadIdx.x;
    int s = k / SBLK, c = k - s * SBLK;
    float v = 0.f;
    if (s < NM && c < 129) {
        int corig = (c == 128) ? 0 : (c + 1);
        v = W[(size_t)(corig * NM + s) * LD + j];
    }
    __half hv = __float2half_rn(v);
    if (LD == 256) g_Wgt[(size_t)j * KPAD + k] = hv;
    else           g_Wct[(size_t)j * KPAD + k] = hv;
}

// ---------------- diffusion pass 1: x0 copy + x1 (=S@x0), all fp16 ------------
template <int USE_RH>
__global__ void __launch_bounds__(128) spmm_pass1(const float* __restrict__ inp) {
    const __half* __restrict__ hvec = USE_RH ? (const __half*)g_rh : (const __half*)g_h16;
    int m = blockIdx.x;
    int g = threadIdx.x >> 5, lane = threadIdx.x & 31;
    int b = blockIdx.y * 4 + g;
    __shared__ int   scol[MAX_NNZ];
    __shared__ float sval[MAX_NNZ];
    __shared__ float sinp[4][MAX_NNZ];
    int cnt = g_csr_cnt[m];
    if (threadIdx.x < MAX_NNZ) {
        scol[threadIdx.x] = g_csr_col[m * MAX_NNZ + threadIdx.x];
        sval[threadIdx.x] = g_csr_val[m * MAX_NNZ + threadIdx.x];
    }
    __syncthreads();
    if (lane < cnt) sinp[g][lane] = inp[(size_t)b * NN + scol[lane]];
    if (cnt > 32 && lane + 32 < cnt) sinp[g][lane + 32] = inp[(size_t)b * NN + scol[lane + 32]];
    __syncwarp();

    size_t rowm = (size_t)b * NN + m;
    float4 a = make_float4(0.f, 0.f, 0.f, 0.f);
    float a1 = 0.f;
    gather_acc_h(hvec + (size_t)b * NN * UU, UU, lane, scol, sval, cnt,
                 sinp[g], a, a1, lane == 0);

    __half* Xh = g_Xh + rowm * KPAD;
    // x0: raw fp16 passthrough (8B per lane)
    *(uint2*)(Xh + lane * 4) = *(const uint2*)(hvec + rowm * UU + lane * 4);
    // x1
    h_store4(Xh + 132 + lane * 4, a);
    if (lane == 0) {
        h_store1pad(Xh + 128, inp[rowm]);   // x0 inp + pads 129..131
        h_store1pad(Xh + 260, a1);          // x1 inp + pads 261..263
    }
}

// ---------------- diffusion pass 2: x2 = 2*S@x1 - x0 (x1 from Xh cols 132+) ---
template <int USE_RH>
__global__ void __launch_bounds__(128) spmm_pass2(const float* __restrict__ inp) {
    const __half* __restrict__ hvec = USE_RH ? (const __half*)g_rh : (const __half*)g_h16;
    int m = blockIdx.x;
    int g = threadIdx.x >> 5, lane = threadIdx.x & 31;
    int b = blockIdx.y * 4 + g;
    __shared__ int   scol[MAX_NNZ];
    __shared__ float sval[MAX_NNZ];
    __shared__ float sx1i[4][MAX_NNZ];
    int cnt = g_csr_cnt[m];
    if (threadIdx.x < MAX_NNZ) {
        scol[threadIdx.x] = g_csr_col[m * MAX_NNZ + threadIdx.x];
        sval[threadIdx.x] = g_csr_val[m * MAX_NNZ + threadIdx.x];
    }
    __syncthreads();
    if (lane < cnt)
        sx1i[g][lane] = __half2float(g_Xh[((size_t)b * NN + scol[lane]) * KPAD + 260]);
    if (cnt > 32 && lane + 32 < cnt)
        sx1i[g][lane + 32] = __half2float(g_Xh[((size_t)b * NN + scol[lane + 32]) * KPAD + 260]);
    __syncwarp();

    size_t rowm = (size_t)b * NN + m;
    float4 a = make_float4(0.f, 0.f, 0.f, 0.f);
    float a1 = 0.f;
    gather_acc_h(g_Xh + (size_t)b * NN * KPAD + 132, KPAD, lane, scol, sval, cnt,
                 sx1i[g], a, a1, lane == 0);

    float4 x0 = h_load4(hvec + rowm * UU + lane * 4);
    float4 r;
    r.x = 2.f * a.x - x0.x;
    r.y = 2.f * a.y - x0.y;
    r.z = 2.f * a.z - x0.z;
    r.w = 2.f * a.w - x0.w;

    __half* Xh = g_Xh + rowm * KPAD;
    h_store4(Xh + 264 + lane * 4, r);                            // cols 264..391
    if (lane == 0) h_store1pad(Xh + 392, 2.f * a1 - inp[rowm]);  // 392..395
    if (lane < 5) {                                              // pads 396..415
        uint2 z; z.x = 0u; z.y = 0u;
        *(uint2*)(Xh + 396 + lane * 4) = z;
    }
}

// ---------------- fp16 tensor-core GEMM ---------------------------------------
// BM=128 BN=128 BK=16, 256 thr (8 warps 4Mx2N), warp tile 32x64, m16n8k16.
// MODE 0: gate (Wgt, N=256, grid.y=2): by0 -> g_rh(fp16) = sig*h ; by1 -> g_u = sig
// MODE 1: cand (Wct, N=128): newh = u*h+(1-u)*tanh ; fused proj -> out
template <int MODE>
__global__ void __launch_bounds__(256) gemm_kernel(
    const float* __restrict__ bias, const float* __restrict__ hvec,
    float* __restrict__ newh, const float* __restrict__ pw,
    const float* __restrict__ pb, float* __restrict__ out)
{
    __shared__ __align__(16) char smem_raw[2 * 2 * 128 * 24 * 2];   // 24576 B
    typedef __half (*SMv)[2][128 * 24];
    SMv SM = (SMv)smem_raw;
    float* srow = (float*)smem_raw;            // aliased; post-mainloop only

    const int tid = threadIdx.x;
    const int lane = tid & 31, wid = tid >> 5;
    const int wm = wid >> 1, wn = wid & 1;
    const size_t mbase = (size_t)blockIdx.x * 128;
    const int jb = (MODE == 0) ? blockIdx.y * 128 : 0;

    const __half* __restrict__ Wt = (MODE == 0) ? g_Wgt : g_Wct;

    const int lrow = tid >> 1, lhalf = tid & 1;
    const __half* srcA = g_Xh + (mbase + lrow) * KPAD + lhalf * 8;
    const __half* srcB = Wt + (size_t)(jb + lrow) * KPAD + lhalf * 8;
    const int dsti = lrow * 24 + lhalf * 8;

    float c[2][8][4];
#pragma unroll
    for (int mt = 0; mt < 2; mt++)
#pragma unroll
        for (int j = 0; j < 8; j++)
#pragma unroll
            for (int q = 0; q < 4; q++) c[mt][j][q] = 0.f;

    {
        cp16(smem_u32(&SM[0][0][dsti]), srcA);
        cp16(smem_u32(&SM[0][1][dsti]), srcB);
        cp_commit();
    }

    const int la = lane & 15;
    const int ka = (lane & 16) ? 8 : 0;
    const int arow = wm * 32 + la;
    const int nb = lane & 7;
    const int kb = (lane & 8) ? 8 : 0;

    for (int t = 0; t < NCH; t++) {
        int cur = t & 1, nxt = cur ^ 1;
        cp_wait0();
        __syncthreads();
        if (t + 1 < NCH) {
            int k0 = (t + 1) * 16;
            cp16(smem_u32(&SM[nxt][0][dsti]), srcA + k0);
            cp16(smem_u32(&SM[nxt][1][dsti]), srcB + k0);
            cp_commit();
        }

        uint32_t ah[2][4];
#pragma unroll
        for (int mt = 0; mt < 2; mt++)
            ldsm_x4(ah[mt], smem_u32(&SM[cur][0][(arow + mt * 16) * 24 + ka]));
#pragma unroll
        for (int j = 0; j < 8; j++) {
            uint32_t bh[2];
            int bi = (wn * 64 + j * 8 + nb) * 24 + kb;
            ldsm_x2(bh, smem_u32(&SM[cur][1][bi]));
#pragma unroll
            for (int mt = 0; mt < 2; mt++)
                mma_f16(c[mt][j], ah[mt], bh);
        }
    }

    // epilogue
    float part[2][2];
    if (MODE == 1) { part[0][0] = part[0][1] = part[1][0] = part[1][1] = 0.f; }

#pragma unroll
    for (int mt = 0; mt < 2; mt++) {
#pragma unroll
        for (int j = 0; j < 8; j++) {
            int row0 = (int)mbase + wm * 32 + mt * 16 + (lane >> 2);
            int col = wn * 64 + j * 8 + (lane & 3) * 2;
            int jg = jb + col;
            float b0 = bias[jg], b1 = bias[jg + 1];
#pragma unroll
            for (int h2 = 0; h2 < 2; h2++) {
                int row = row0 + h2 * 8;
                float v0 = c[mt][j][h2 * 2 + 0] + b0;
                float v1 = c[mt][j][h2 * 2 + 1] + b1;
                size_t idx = (size_t)row * UU + col;
                if (MODE == 0) {
                    float s0 = 1.f / (1.f + expf(-v0));
                    float s1 = 1.f / (1.f + expf(-v1));
                    if (jb == 0) {
                        float2 hh = *(const float2*)(hvec + idx);
                        __half2 o = __floats2half2_rn(s0 * hh.x, s1 * hh.y);
                        *(__half2*)(g_rh + idx) = o;
                    } else {
                        float2 o; o.x = s0; o.y = s1;
                        *(float2*)(g_u + idx) = o;
                    }
                } else {
                    float t0 = tanhf(v0), t1 = tanhf(v1);
                    float2 uu = *(const float2*)(g_u + idx);
                    float2 hh = *(const float2*)(hvec + idx);
                    float2 o;
                    o.x = uu.x * hh.x + (1.f - uu.x) * t0;
                    o.y = uu.y * hh.y + (1.f - uu.y) * t1;
                    *(float2*)(newh + idx) = o;
                    part[mt][h2] = fmaf(o.x, pw[col], part[mt][h2]);
                    part[mt][h2] = fmaf(o.y, pw[col + 1], part[mt][h2]);
                }
            }
        }
    }

    if (MODE == 1) {
        __syncthreads();               // SM reads done; safe to alias srow
        if (tid < 128) srow[tid] = 0.f;
        __syncthreads();
#pragma unroll
        for (int mt = 0; mt < 2; mt++)
#pragma unroll
            for (int h2 = 0; h2 < 2; h2++) {
                int lr = wm * 32 + mt * 16 + h2 * 8 + (lane >> 2);
                atomicAdd(&srow[lr], part[mt][h2]);
            }
        __syncthreads();
        if (tid < 128) out[mbase + tid] = srow[tid] + pb[0];
    }
}

// ---------------- launch ------------------------------------------------------
extern "C" void kernel_launch(void* const* d_in, const int* in_sizes, int n_in,
                              void* d_out, int out_size) {
    const float* inp = (const float*)d_in[0];
    const float* h   = (const float*)d_in[1];
    const float* S   = (const float*)d_in[2];
    const float* gw  = (const float*)d_in[3];
    const float* gb  = (const float*)d_in[4];
    const float* cw  = (const float*)d_in[5];
    const float* cb  = (const float*)d_in[6];
    const float* pw  = (const float*)d_in[7];
    const float* pb  = (const float*)d_in[8];
    float* out  = (float*)d_out;
    float* newh = out + MROWS;

    csr_build<<<128, 256>>>(S);
    wtrans<256><<<KPAD, 256>>>(gw);
    wtrans<128><<<KPAD, 128>>>(cw);
    h2half<<<MROWS * UU / 1024, 256>>>(h);

    // gate path
    spmm_pass1<0><<<dim3(NN, BB / 4), 128>>>(inp);
    spmm_pass2<0><<<dim3(NN, BB / 4), 128>>>(inp);
    gemm_kernel<0><<<dim3(MROWS / 128, 2), 256>>>(gb, h, nullptr, nullptr, nullptr, nullptr);

    // cand path (projection fused)
    spmm_pass1<1><<<dim3(NN, BB / 4), 128>>>(inp);
    spmm_pass2<1><<<dim3(NN, BB / 4), 128>>>(inp);
    gemm_kernel<1><<<dim3(MROWS / 128, 1), 256>>>(cb, h, newh, pw, pb, out);
}